// round 2
// baseline (speedup 1.0000x reference)
#include <cuda_runtime.h>
#include <cuda_bf16.h>
#include <cstdint>

// Problem constants
#define NIMG 8
#define NGT  256
#define NPR  8000
#define NPAD 8192            // next pow2 >= NPR for bitonic sort
#define BATCH 512
#define NPOSMAX 128

// ---------------------------------------------------------------------------
// Threefry-2x32 (JAX default PRNG), 20 rounds.
// ---------------------------------------------------------------------------
__host__ __device__ __forceinline__ void threefry2x32(
    uint32_t k0, uint32_t k1, uint32_t x0, uint32_t x1,
    uint32_t& o0, uint32_t& o1)
{
    uint32_t ks0 = k0, ks1 = k1, ks2 = k0 ^ k1 ^ 0x1BD11BDAu;
    uint32_t a = x0 + ks0, b = x1 + ks1;
    const uint32_t rot[2][4] = {{13u,15u,26u,6u},{17u,29u,16u,24u}};
#pragma unroll
    for (int i = 0; i < 5; ++i) {
        const uint32_t* r = rot[i & 1];
#pragma unroll
        for (int q = 0; q < 4; ++q) {
            a += b;
            b = (b << r[q]) | (b >> (32u - r[q]));
            b ^= a;
        }
        // key injection after each group of 4 rounds
        uint32_t i1 = (uint32_t)(i + 1);
        uint32_t kA = (i % 3 == 0) ? ks1 : (i % 3 == 1) ? ks2 : ks0;   // ks[(i+1)%3]
        uint32_t kB = (i % 3 == 0) ? ks2 : (i % 3 == 1) ? ks0 : ks1;   // ks[(i+2)%3]
        a += kA;
        b += kB + i1;
    }
    o0 = a; o1 = b;
}

// Partitionable-mode 32-bit random bits for element i of a 1-D draw:
// b1, b2 = threefry(key, (hi32(i), lo32(i))) ; bits = b1 ^ b2
__host__ __device__ __forceinline__ uint32_t jax_random_bits32(
    uint32_t k0, uint32_t k1, uint32_t idx)
{
    uint32_t w0, w1;
    threefry2x32(k0, k1, 0u, idx, w0, w1);
    return w0 ^ w1;
}

// uniform [0,1) float from a raw 32-bit word, exactly as jax.random.uniform
__host__ __device__ __forceinline__ float jax_uniform_from_bits(uint32_t bits) {
    uint32_t fb = (bits >> 9) | 0x3f800000u;
    float f;
#ifdef __CUDA_ARCH__
    f = __uint_as_float(fb);
#else
    union { uint32_t u; float f; } c; c.u = fb; f = c.f;
#endif
    return f - 1.0f;
}

struct ImgKeys {
    // per image: k1 (2 words), k2 (2 words)
    uint32_t v[NIMG][4];
};

// ---------------------------------------------------------------------------
// Scratch (device globals — no allocation allowed)
// ---------------------------------------------------------------------------
__device__ int                g_midx[NIMG * NPR];
__device__ int                g_labels[NIMG * NPR];
__device__ unsigned long long g_fgkeys[NIMG * NPR];
__device__ unsigned long long g_bgkeys[NIMG * NPR];
__device__ int                g_fginds[NIMG * NPOSMAX];
__device__ int                g_bginds[NIMG * BATCH];
__device__ int                g_counts[NIMG * 2];

// ---------------------------------------------------------------------------
// Kernel 1: IoU matching + labels + PRNG sort keys.
// One thread per proposal. GT boxes staged in shared memory.
// All float ops use *_rn intrinsics to forbid FMA contraction (must match the
// reference's individually-rounded fp32 arithmetic for argmax / >=0.5 ties).
// ---------------------------------------------------------------------------
__global__ void match_kernel(const float* __restrict__ gt,
                             const int*   __restrict__ gtc,
                             const float* __restrict__ pr,
                             ImgKeys keys)
{
    const int img = blockIdx.y;
    const int r   = blockIdx.x * blockDim.x + threadIdx.x;

    __shared__ float4 sgt[NGT];
    __shared__ float  sag[NGT];
    __shared__ int    sgc[NGT];

    // blockDim.x == 256 == NGT: each thread stages one gt box
    {
        const int t = threadIdx.x;
        float4 g = reinterpret_cast<const float4*>(gt)[img * NGT + t];
        sgt[t] = g;
        sag[t] = __fmul_rn(__fsub_rn(g.z, g.x), __fsub_rn(g.w, g.y));
        sgc[t] = gtc[img * NGT + t];
    }
    __syncthreads();

    if (r >= NPR) return;

    float4 p = reinterpret_cast<const float4*>(pr)[img * NPR + r];
    const float ap = __fmul_rn(__fsub_rn(p.z, p.x), __fsub_rn(p.w, p.y));

    float best = -1.0f;
    int   bi   = 0;
#pragma unroll 4
    for (int m = 0; m < NGT; ++m) {
        float4 g = sgt[m];
        float lx = fmaxf(g.x, p.x);
        float ly = fmaxf(g.y, p.y);
        float rx = fminf(g.z, p.z);
        float ry = fminf(g.w, p.w);
        float wx = fmaxf(__fsub_rn(rx, lx), 0.0f);
        float wy = fmaxf(__fsub_rn(ry, ly), 0.0f);
        float inter = __fmul_rn(wx, wy);
        float uni   = __fsub_rn(__fadd_rn(sag[m], ap), inter);
        float iou   = __fdiv_rn(inter, uni);
        if (iou > best) { best = iou; bi = m; }   // first-max tie-break
    }

    const bool fg = (best >= 0.5f);               // FG_IOU == BG_IOU == 0.5
    const int  label = fg ? sgc[bi] : 0;

    g_midx[img * NPR + r]   = bi;
    g_labels[img * NPR + r] = label;

    // Partitionable-threefry random bits for this element of each draw
    const uint32_t* kv = keys.v[img];
    uint32_t bits1 = jax_random_bits32(kv[0], kv[1], (uint32_t)r);
    uint32_t bits2 = jax_random_bits32(kv[2], kv[3], (uint32_t)r);

    float u1 = jax_uniform_from_bits(bits1);
    float u2 = jax_uniform_from_bits(bits2);

    const unsigned long long INVALID_HI = 0x40000000ull << 32;  // bits of 2.0f
    unsigned long long fk = fg
        ? (((unsigned long long)__float_as_uint(u1)) << 32) | (unsigned)r
        : INVALID_HI | (unsigned)r;
    unsigned long long bk = (!fg)
        ? (((unsigned long long)__float_as_uint(u2)) << 32) | (unsigned)r
        : INVALID_HI | (unsigned)r;

    g_fgkeys[img * NPR + r] = fk;
    g_bgkeys[img * NPR + r] = bk;
}

// ---------------------------------------------------------------------------
// Kernel 2: per-(image, pool) bitonic sort of 8192 u64 keys in shared memory.
// Emits the first 128 (fg) / 512 (bg) indices in ascending-score order, plus
// the count of valid (score < 2.0) entries via binary search.
// ---------------------------------------------------------------------------
__global__ void sort_kernel()
{
    extern __shared__ unsigned long long s[];
    const int img   = blockIdx.x >> 1;
    const int which = blockIdx.x & 1;     // 0 = fg, 1 = bg
    const unsigned long long* src = which == 0 ? g_fgkeys : g_bgkeys;

    for (int i = threadIdx.x; i < NPAD; i += blockDim.x)
        s[i] = (i < NPR) ? src[img * NPR + i] : ~0ull;
    __syncthreads();

    for (int k = 2; k <= NPAD; k <<= 1) {
        for (int j = k >> 1; j > 0; j >>= 1) {
            for (int i = threadIdx.x; i < NPAD; i += blockDim.x) {
                int ixj = i ^ j;
                if (ixj > i) {
                    bool up = ((i & k) == 0);
                    unsigned long long a = s[i], b = s[ixj];
                    if ((a > b) == up) { s[i] = b; s[ixj] = a; }
                }
            }
            __syncthreads();
        }
    }

    if (which == 0) {
        for (int i = threadIdx.x; i < NPOSMAX; i += blockDim.x)
            g_fginds[img * NPOSMAX + i] = (int)(unsigned)(s[i] & 0xffffffffu);
    } else {
        for (int i = threadIdx.x; i < BATCH; i += blockDim.x)
            g_bginds[img * BATCH + i] = (int)(unsigned)(s[i] & 0xffffffffu);
    }
    if (threadIdx.x == 0) {
        const unsigned long long T = 0x4000000000000000ull;  // 2.0f << 32
        int lo = 0, hi = NPAD;
        while (lo < hi) {
            int mid = (lo + hi) >> 1;
            if (s[mid] < T) lo = mid + 1; else hi = mid;
        }
        g_counts[img * 2 + which] = lo;
    }
}

// ---------------------------------------------------------------------------
// Kernel 3: assemble outputs.
// Layout: [8*512*8 floats of boxes | 8*512 floats of classes]
// ---------------------------------------------------------------------------
__global__ void gather_kernel(const float* __restrict__ gt,
                              const float* __restrict__ pr,
                              float* __restrict__ out)
{
    const int img  = blockIdx.x;
    const int slot = threadIdx.x;   // 0..511

    const int fgc = g_counts[img * 2 + 0];
    const int bgc = g_counts[img * 2 + 1];
    const int np  = min(fgc, NPOSMAX);
    const int nn  = min(bgc, BATCH - np);

    int sampled;
    if (slot < np) {
        sampled = g_fginds[img * NPOSMAX + min(slot, NPOSMAX - 1)];
    } else {
        sampled = g_bginds[img * BATCH + min(slot - np, BATCH - 1)];
    }
    const bool valid = slot < (np + nn);
    const float v = valid ? 1.0f : 0.0f;

    const int m = g_midx[img * NPR + sampled];
    float4 p = reinterpret_cast<const float4*>(pr)[img * NPR + sampled];
    float4 g = reinterpret_cast<const float4*>(gt)[img * NGT + m];

    float* ob = out + (size_t)(img * BATCH + slot) * 8;
    ob[0] = p.x * v;  ob[1] = p.y * v;  ob[2] = p.z * v;  ob[3] = p.w * v;
    ob[4] = g.x * v;  ob[5] = g.y * v;  ob[6] = g.z * v;  ob[7] = g.w * v;

    const int cls = valid ? g_labels[img * NPR + sampled] : -1;
    out[(size_t)NIMG * BATCH * 8 + img * BATCH + slot] = (float)cls;
}

// ---------------------------------------------------------------------------
// Host: derive per-image (k1, k2) Threefry keys, PARTITIONABLE mode:
//   root = key(42) = (0, 42)
//   keys[i]  = TF(root, (0, i))          (foldlike split over 64-bit iota)
//   k1, k2   = TF(keys[i], (0,0)), TF(keys[i], (0,1))
// ---------------------------------------------------------------------------
static void compute_keys(ImgKeys& out)
{
    for (int i = 0; i < NIMG; ++i) {
        uint32_t ik0, ik1;
        threefry2x32(0u, 42u, 0u, (uint32_t)i, ik0, ik1);
        uint32_t a0, a1, b0, b1;
        threefry2x32(ik0, ik1, 0u, 0u, a0, a1);   // k1
        threefry2x32(ik0, ik1, 0u, 1u, b0, b1);   // k2
        out.v[i][0] = a0; out.v[i][1] = a1;
        out.v[i][2] = b0; out.v[i][3] = b1;
    }
}

extern "C" void kernel_launch(void* const* d_in, const int* in_sizes, int n_in,
                              void* d_out, int out_size)
{
    const float* gt  = (const float*)d_in[0];  // [8,256,4]
    const int*   gtc = (const int*)  d_in[1];  // [8,256]
    const float* pr  = (const float*)d_in[2];  // [8,8000,4]
    float* out = (float*)d_out;

    (void)in_sizes; (void)n_in; (void)out_size;

    ImgKeys keys;
    compute_keys(keys);

    // allow 64 KB dynamic smem for the bitonic sort
    cudaFuncSetAttribute(sort_kernel,
                         cudaFuncAttributeMaxDynamicSharedMemorySize,
                         NPAD * (int)sizeof(unsigned long long));

    dim3 g1((NPR + 255) / 256, NIMG);
    match_kernel<<<g1, 256>>>(gt, gtc, pr, keys);
    sort_kernel<<<NIMG * 2, 1024, NPAD * sizeof(unsigned long long)>>>();
    gather_kernel<<<NIMG, BATCH>>>(gt, pr, out);
}

// round 3
// speedup vs baseline: 2.3889x; 2.3889x over previous
#include <cuda_runtime.h>
#include <cuda_bf16.h>
#include <cstdint>

// Problem constants
#define NIMG 8
#define NGT  256
#define NPR  8000
#define BATCH 512
#define NPOSMAX 128

#define CAND_CAP 2048        // candidate buffer for selection (pow2)
#define NBUCKET 1024

// ---------------------------------------------------------------------------
// Threefry-2x32 (JAX default PRNG), 20 rounds.
// ---------------------------------------------------------------------------
__host__ __device__ __forceinline__ void threefry2x32(
    uint32_t k0, uint32_t k1, uint32_t x0, uint32_t x1,
    uint32_t& o0, uint32_t& o1)
{
    uint32_t ks0 = k0, ks1 = k1, ks2 = k0 ^ k1 ^ 0x1BD11BDAu;
    uint32_t a = x0 + ks0, b = x1 + ks1;
    const uint32_t rot[2][4] = {{13u,15u,26u,6u},{17u,29u,16u,24u}};
#pragma unroll
    for (int i = 0; i < 5; ++i) {
        const uint32_t* r = rot[i & 1];
#pragma unroll
        for (int q = 0; q < 4; ++q) {
            a += b;
            b = (b << r[q]) | (b >> (32u - r[q]));
            b ^= a;
        }
        uint32_t i1 = (uint32_t)(i + 1);
        uint32_t kA = (i % 3 == 0) ? ks1 : (i % 3 == 1) ? ks2 : ks0;
        uint32_t kB = (i % 3 == 0) ? ks2 : (i % 3 == 1) ? ks0 : ks1;
        a += kA;
        b += kB + i1;
    }
    o0 = a; o1 = b;
}

// Partitionable-mode 32-bit random bits for element i of a 1-D draw:
__host__ __device__ __forceinline__ uint32_t jax_random_bits32(
    uint32_t k0, uint32_t k1, uint32_t idx)
{
    uint32_t w0, w1;
    threefry2x32(k0, k1, 0u, idx, w0, w1);
    return w0 ^ w1;
}

__host__ __device__ __forceinline__ float jax_uniform_from_bits(uint32_t bits) {
    uint32_t fb = (bits >> 9) | 0x3f800000u;
    float f;
#ifdef __CUDA_ARCH__
    f = __uint_as_float(fb);
#else
    union { uint32_t u; float f; } c; c.u = fb; f = c.f;
#endif
    return f - 1.0f;
}

struct ImgKeys {
    uint32_t v[NIMG][4];   // per image: k1 (2 words), k2 (2 words)
};

// ---------------------------------------------------------------------------
// Scratch (device globals — no allocation allowed)
// ---------------------------------------------------------------------------
__device__ int                g_midx[NIMG * NPR];
__device__ int                g_labels[NIMG * NPR];
__device__ unsigned long long g_fgkeys[NIMG * NPR];
__device__ unsigned long long g_bgkeys[NIMG * NPR];
__device__ int                g_fginds[NIMG * NPOSMAX];
__device__ int                g_bginds[NIMG * BATCH];
__device__ int                g_counts[NIMG * 2];

// ---------------------------------------------------------------------------
// Kernel 1: IoU matching + labels + PRNG sort keys.
// Division-avoidance: iou = inter/uni is only computed when it could beat
// `best`. If inter==0 -> iou==0 exactly. If best>0 and
// inter < __fmul_rd(best, uni) <= best*uni (real), then inter/uni < best
// (real), so rn(inter/uni) <= best and the strict '>' update cannot fire.
// All computed values are bit-identical to the reference path.
// ---------------------------------------------------------------------------
__global__ void match_kernel(const float* __restrict__ gt,
                             const int*   __restrict__ gtc,
                             const float* __restrict__ pr,
                             ImgKeys keys)
{
    const int img = blockIdx.y;
    const int r   = blockIdx.x * blockDim.x + threadIdx.x;

    __shared__ float4 sgt[NGT];
    __shared__ float  sag[NGT];
    __shared__ int    sgc[NGT];

    {
        const int t = threadIdx.x;   // blockDim.x == 256 == NGT
        float4 g = reinterpret_cast<const float4*>(gt)[img * NGT + t];
        sgt[t] = g;
        sag[t] = __fmul_rn(__fsub_rn(g.z, g.x), __fsub_rn(g.w, g.y));
        sgc[t] = gtc[img * NGT + t];
    }
    __syncthreads();

    if (r >= NPR) return;

    float4 p = reinterpret_cast<const float4*>(pr)[img * NPR + r];
    const float ap = __fmul_rn(__fsub_rn(p.z, p.x), __fsub_rn(p.w, p.y));

    float best = -1.0f;
    int   bi   = 0;
#pragma unroll 4
    for (int m = 0; m < NGT; ++m) {
        float4 g = sgt[m];
        float lx = fmaxf(g.x, p.x);
        float ly = fmaxf(g.y, p.y);
        float rx = fminf(g.z, p.z);
        float ry = fminf(g.w, p.w);
        float wx = fmaxf(__fsub_rn(rx, lx), 0.0f);
        float wy = fmaxf(__fsub_rn(ry, ly), 0.0f);
        float inter = __fmul_rn(wx, wy);
        if (inter == 0.0f) {
            if (best < 0.0f) { best = 0.0f; bi = m; }
        } else {
            float uni = __fsub_rn(__fadd_rn(sag[m], ap), inter);
            if (!(best > 0.0f) || inter >= __fmul_rd(best, uni)) {
                float iou = __fdiv_rn(inter, uni);
                if (iou > best) { best = iou; bi = m; }   // first-max tie-break
            }
        }
    }

    const bool fg = (best >= 0.5f);               // FG_IOU == BG_IOU == 0.5
    const int  label = fg ? sgc[bi] : 0;

    g_midx[img * NPR + r]   = bi;
    g_labels[img * NPR + r] = label;

    const uint32_t* kv = keys.v[img];
    uint32_t bits1 = jax_random_bits32(kv[0], kv[1], (uint32_t)r);
    uint32_t bits2 = jax_random_bits32(kv[2], kv[3], (uint32_t)r);

    float u1 = jax_uniform_from_bits(bits1);
    float u2 = jax_uniform_from_bits(bits2);

    const unsigned long long INVALID_HI = 0x40000000ull << 32;  // bits of 2.0f
    unsigned long long fk = fg
        ? (((unsigned long long)__float_as_uint(u1)) << 32) | (unsigned)r
        : INVALID_HI | (unsigned)r;
    unsigned long long bk = (!fg)
        ? (((unsigned long long)__float_as_uint(u2)) << 32) | (unsigned)r
        : INVALID_HI | (unsigned)r;

    g_fgkeys[img * NPR + r] = fk;
    g_bgkeys[img * NPR + r] = bk;
}

// ---------------------------------------------------------------------------
// Kernel 2: histogram-select + small bitonic sort per (image, pool).
// Exactly reproduces "first `target` entries of a stable ascending argsort":
//   - bucket = floor(u * 1024) is monotone in u (and in the u64 key's hi32),
//     so candidates (buckets <= B, where cum[B] >= target) are a superset of
//     the bottom-target keys.
//   - full u64 sort of candidates gives exact (score, index) order.
// blockDim must be 1024 (== NBUCKET).
// ---------------------------------------------------------------------------
__global__ void select_kernel()
{
    extern __shared__ unsigned long long dyn[];
    unsigned long long* skeys = dyn;                           // [NPR]
    unsigned long long* cand  = dyn + NPR;                     // [CAND_CAP]
    int* hist = (int*)(cand + CAND_CAP);                       // [NBUCKET]
    int* cum  = hist + NBUCKET;                                // [NBUCKET]
    int* misc = cum + NBUCKET;                                 // [0]=cnt [1]=B

    const int tid   = threadIdx.x;
    const int img   = blockIdx.x >> 1;
    const int which = blockIdx.x & 1;     // 0 = fg, 1 = bg
    const int target = (which == 0) ? NPOSMAX : BATCH;
    const unsigned long long* src = which == 0 ? g_fgkeys : g_bgkeys;

    hist[tid] = 0;
    if (tid == 0) { misc[0] = 0; misc[1] = NBUCKET - 1; }
    __syncthreads();

    // Pass 1: load keys to smem + histogram of valid entries
    for (int i = tid; i < NPR; i += 1024) {
        unsigned long long k = src[img * NPR + i];
        skeys[i] = k;
        uint32_t hi = (uint32_t)(k >> 32);
        if (hi < 0x40000000u) {                       // valid (score < 2.0)
            float f = __uint_as_float(hi);
            int b = (int)(f * (float)NBUCKET);        // monotone, 0..1023
            atomicAdd(&hist[b], 1);
        }
    }
    __syncthreads();

    // Inclusive scan of hist (Hillis-Steele ping-pong), 1024 threads
    int* s = hist; int* d = cum;
#pragma unroll
    for (int off = 1; off < NBUCKET; off <<= 1) {
        int v = s[tid];
        if (tid >= off) v += s[tid - off];
        __syncthreads();
        d[tid] = v;
        __syncthreads();
        int* t = s; s = d; d = t;
    }
    // result in s
    const int total = s[NBUCKET - 1];
    if (s[tid] >= target && (tid == 0 || s[tid - 1] < target))
        misc[1] = tid;
    __syncthreads();
    const int B = misc[1];

    // Init candidate pad, then compact candidates (buckets <= B)
    for (int i = tid; i < CAND_CAP; i += 1024) cand[i] = ~0ull;
    __syncthreads();
    for (int i = tid; i < NPR; i += 1024) {
        unsigned long long k = skeys[i];
        uint32_t hi = (uint32_t)(k >> 32);
        if (hi < 0x40000000u) {
            float f = __uint_as_float(hi);
            int b = (int)(f * (float)NBUCKET);
            if (b <= B) {
                int pos = atomicAdd(&misc[0], 1);
                if (pos < CAND_CAP) cand[pos] = k;
            }
        }
    }
    __syncthreads();
    const int cnt = min(misc[0], CAND_CAP);

    // Bitonic sort of CAND_CAP u64 keys (ascending)
    for (int k = 2; k <= CAND_CAP; k <<= 1) {
        for (int j = k >> 1; j > 0; j >>= 1) {
            for (int i = tid; i < CAND_CAP; i += 1024) {
                int ixj = i ^ j;
                if (ixj > i) {
                    bool up = ((i & k) == 0);
                    unsigned long long a = cand[i], b2 = cand[ixj];
                    if ((a > b2) == up) { cand[i] = b2; cand[ixj] = a; }
                }
            }
            __syncthreads();
        }
    }

    // Emit first `target` indices (0-clamped beyond valid count) + total
    if (which == 0) {
        if (tid < NPOSMAX) {
            int idx = (tid < cnt) ? (int)(unsigned)(cand[tid] & 0xffffffffu) : 0;
            g_fginds[img * NPOSMAX + tid] = idx;
        }
    } else {
        if (tid < BATCH) {
            int idx = (tid < cnt) ? (int)(unsigned)(cand[tid] & 0xffffffffu) : 0;
            g_bginds[img * BATCH + tid] = idx;
        }
    }
    if (tid == 0) g_counts[img * 2 + which] = total;
}

// ---------------------------------------------------------------------------
// Kernel 3: assemble outputs.
// Layout: [8*512*8 floats of boxes | 8*512 floats of classes]
// ---------------------------------------------------------------------------
__global__ void gather_kernel(const float* __restrict__ gt,
                              const float* __restrict__ pr,
                              float* __restrict__ out)
{
    const int img  = blockIdx.x;
    const int slot = threadIdx.x;   // 0..511

    const int fgc = g_counts[img * 2 + 0];
    const int bgc = g_counts[img * 2 + 1];
    const int np  = min(fgc, NPOSMAX);
    const int nn  = min(bgc, BATCH - np);

    int sampled;
    if (slot < np) {
        sampled = g_fginds[img * NPOSMAX + min(slot, NPOSMAX - 1)];
    } else {
        sampled = g_bginds[img * BATCH + min(slot - np, BATCH - 1)];
    }
    const bool valid = slot < (np + nn);
    const float v = valid ? 1.0f : 0.0f;

    const int m = g_midx[img * NPR + sampled];
    float4 p = reinterpret_cast<const float4*>(pr)[img * NPR + sampled];
    float4 g = reinterpret_cast<const float4*>(gt)[img * NGT + m];

    float* ob = out + (size_t)(img * BATCH + slot) * 8;
    ob[0] = p.x * v;  ob[1] = p.y * v;  ob[2] = p.z * v;  ob[3] = p.w * v;
    ob[4] = g.x * v;  ob[5] = g.y * v;  ob[6] = g.z * v;  ob[7] = g.w * v;

    const int cls = valid ? g_labels[img * NPR + sampled] : -1;
    out[(size_t)NIMG * BATCH * 8 + img * BATCH + slot] = (float)cls;
}

// ---------------------------------------------------------------------------
// Host: per-image (k1, k2) Threefry keys, partitionable mode:
//   root = key(42) = (0, 42)
//   keys[i]  = TF(root, (0, i))
//   k1, k2   = TF(keys[i], (0,0)), TF(keys[i], (0,1))
// ---------------------------------------------------------------------------
static void compute_keys(ImgKeys& out)
{
    for (int i = 0; i < NIMG; ++i) {
        uint32_t ik0, ik1;
        threefry2x32(0u, 42u, 0u, (uint32_t)i, ik0, ik1);
        uint32_t a0, a1, b0, b1;
        threefry2x32(ik0, ik1, 0u, 0u, a0, a1);   // k1
        threefry2x32(ik0, ik1, 0u, 1u, b0, b1);   // k2
        out.v[i][0] = a0; out.v[i][1] = a1;
        out.v[i][2] = b0; out.v[i][3] = b1;
    }
}

extern "C" void kernel_launch(void* const* d_in, const int* in_sizes, int n_in,
                              void* d_out, int out_size)
{
    const float* gt  = (const float*)d_in[0];  // [8,256,4]
    const int*   gtc = (const int*)  d_in[1];  // [8,256]
    const float* pr  = (const float*)d_in[2];  // [8,8000,4]
    float* out = (float*)d_out;

    (void)in_sizes; (void)n_in; (void)out_size;

    ImgKeys keys;
    compute_keys(keys);

    const int select_smem =
        (NPR + CAND_CAP) * (int)sizeof(unsigned long long) +
        (2 * NBUCKET + 2) * (int)sizeof(int);
    cudaFuncSetAttribute(select_kernel,
                         cudaFuncAttributeMaxDynamicSharedMemorySize,
                         select_smem);

    dim3 g1((NPR + 255) / 256, NIMG);
    match_kernel<<<g1, 256>>>(gt, gtc, pr, keys);
    select_kernel<<<NIMG * 2, 1024, select_smem>>>();
    gather_kernel<<<NIMG, BATCH>>>(gt, pr, out);
}

// round 4
// speedup vs baseline: 3.1011x; 1.2981x over previous
#include <cuda_runtime.h>
#include <cuda_bf16.h>
#include <cstdint>

// Problem constants
#define NIMG 8
#define NGT  256
#define NPR  8000
#define BATCH 512
#define NPOSMAX 128

#define CAND_CAP 2048        // candidate buffer for selection (pow2)
#define NBUCKET 1024

// ---------------------------------------------------------------------------
// Threefry-2x32 (JAX default PRNG), 20 rounds.
// ---------------------------------------------------------------------------
__host__ __device__ __forceinline__ void threefry2x32(
    uint32_t k0, uint32_t k1, uint32_t x0, uint32_t x1,
    uint32_t& o0, uint32_t& o1)
{
    uint32_t ks0 = k0, ks1 = k1, ks2 = k0 ^ k1 ^ 0x1BD11BDAu;
    uint32_t a = x0 + ks0, b = x1 + ks1;
    const uint32_t rot[2][4] = {{13u,15u,26u,6u},{17u,29u,16u,24u}};
#pragma unroll
    for (int i = 0; i < 5; ++i) {
        const uint32_t* r = rot[i & 1];
#pragma unroll
        for (int q = 0; q < 4; ++q) {
            a += b;
            b = (b << r[q]) | (b >> (32u - r[q]));
            b ^= a;
        }
        uint32_t i1 = (uint32_t)(i + 1);
        uint32_t kA = (i % 3 == 0) ? ks1 : (i % 3 == 1) ? ks2 : ks0;
        uint32_t kB = (i % 3 == 0) ? ks2 : (i % 3 == 1) ? ks0 : ks1;
        a += kA;
        b += kB + i1;
    }
    o0 = a; o1 = b;
}

__host__ __device__ __forceinline__ float jax_uniform_from_bits(uint32_t bits) {
    uint32_t fb = (bits >> 9) | 0x3f800000u;
    float f;
#ifdef __CUDA_ARCH__
    f = __uint_as_float(fb);
#else
    union { uint32_t u; float f; } c; c.u = fb; f = c.f;
#endif
    return f - 1.0f;
}

struct ImgKeys {
    uint32_t v[NIMG][4];   // per image: k1 (2 words), k2 (2 words)
};

// ---------------------------------------------------------------------------
// Scratch (device globals — no allocation allowed)
// ---------------------------------------------------------------------------
__device__ int                g_midx[NIMG * NPR];
__device__ int                g_labels[NIMG * NPR];
__device__ unsigned long long g_fgkeys[NIMG * NPR];
__device__ unsigned long long g_bgkeys[NIMG * NPR];
__device__ int                g_fginds[NIMG * NPOSMAX];
__device__ int                g_bginds[NIMG * BATCH];
__device__ int                g_counts[NIMG * 2];

// ---------------------------------------------------------------------------
// Kernel 1: IoU matching + labels + PRNG sort keys.
// 4 threads per proposal (sub = tid & 3); sub handles interleaved GT subset
// m = sub, sub+4, ... (conflict-free SMEM broadcast), then a shfl.xor argmax
// reduction with (max value, min index) combine — identical to sequential
// first-max over all 256 GTs.
// Division-avoidance: iou = inter/uni is only computed when it could beat
// `best` (proof in round-2 notes); all computed values bit-match the ref.
// ---------------------------------------------------------------------------
__global__ void match_kernel(const float* __restrict__ gt,
                             const int*   __restrict__ gtc,
                             const float* __restrict__ pr,
                             ImgKeys keys)
{
    const int img = blockIdx.y;
    const int tid = threadIdx.x;           // 256 threads = 64 proposals x 4
    const int sub = tid & 3;
    const int r   = blockIdx.x * 64 + (tid >> 2);   // 8000 / 64 = 125 blocks

    __shared__ float4 sgt[NGT];
    __shared__ float  sag[NGT];
    __shared__ int    sgc[NGT];

    {
        float4 g = reinterpret_cast<const float4*>(gt)[img * NGT + tid];
        sgt[tid] = g;
        sag[tid] = __fmul_rn(__fsub_rn(g.z, g.x), __fsub_rn(g.w, g.y));
        sgc[tid] = gtc[img * NGT + tid];
    }
    __syncthreads();

    float4 p = reinterpret_cast<const float4*>(pr)[img * NPR + r];
    const float ap = __fmul_rn(__fsub_rn(p.z, p.x), __fsub_rn(p.w, p.y));

    float best = -1.0f;
    int   bi   = sub;          // first index this thread will visit
#pragma unroll 8
    for (int i = 0; i < NGT / 4; ++i) {
        const int m = sub + 4 * i;
        float4 g = sgt[m];
        float lx = fmaxf(g.x, p.x);
        float ly = fmaxf(g.y, p.y);
        float rx = fminf(g.z, p.z);
        float ry = fminf(g.w, p.w);
        float wx = fmaxf(__fsub_rn(rx, lx), 0.0f);
        float wy = fmaxf(__fsub_rn(ry, ly), 0.0f);
        float inter = __fmul_rn(wx, wy);
        if (inter == 0.0f) {
            if (best < 0.0f) { best = 0.0f; bi = m; }
        } else {
            float uni = __fsub_rn(__fadd_rn(sag[m], ap), inter);
            if (!(best > 0.0f) || inter >= __fmul_rd(best, uni)) {
                float iou = __fdiv_rn(inter, uni);
                if (iou > best) { best = iou; bi = m; }   // first-max tie-break
            }
        }
    }

    // Reduce across the 4 subs (groups of 4 lanes are xor-1/2 closed)
#pragma unroll
    for (int off = 1; off <= 2; off <<= 1) {
        float ob = __shfl_xor_sync(0xffffffffu, best, off);
        int  obi = __shfl_xor_sync(0xffffffffu, bi,   off);
        if (ob > best || (ob == best && obi < bi)) { best = ob; bi = obi; }
    }

    const bool fg = (best >= 0.5f);        // FG_IOU == BG_IOU == 0.5

    // One converged Threefry per lane: subs 0/1 use k1, subs 2/3 use k2.
    const uint32_t* kv = keys.v[img];
    uint32_t kk0 = (sub & 2) ? kv[2] : kv[0];
    uint32_t kk1 = (sub & 2) ? kv[3] : kv[1];
    uint32_t w0, w1;
    threefry2x32(kk0, kk1, 0u, (uint32_t)r, w0, w1);
    float u = jax_uniform_from_bits(w0 ^ w1);

    const unsigned long long INVALID = (0x40000000ull << 32) | (unsigned)r;
    unsigned long long keyv =
        (((unsigned long long)__float_as_uint(u)) << 32) | (unsigned)r;

    if (sub == 0) g_fgkeys[img * NPR + r] = fg ? keyv : INVALID;
    if (sub == 2) g_bgkeys[img * NPR + r] = fg ? INVALID : keyv;
    if (sub == 1) g_midx[img * NPR + r] = bi;
    if (sub == 3) g_labels[img * NPR + r] = fg ? sgc[bi] : 0;
}

// ---------------------------------------------------------------------------
// Kernel 2: histogram-select + adaptive bitonic sort per (image, pool).
// Exactly reproduces "first `target` entries of a stable ascending argsort":
// bucket = floor(u * 1024) is monotone in u, so buckets <= B (cum >= target)
// are a superset of the bottom-target keys; full u64 sort of candidates gives
// exact (score, index) order. blockDim must be 1024.
// ---------------------------------------------------------------------------
__global__ void select_kernel()
{
    __shared__ unsigned long long cand[CAND_CAP];
    __shared__ int hist[NBUCKET];
    __shared__ int cum[NBUCKET];
    __shared__ int wsum[32];
    __shared__ int misc[2];     // [0]=cnt  [1]=B

    const int tid   = threadIdx.x;
    const int lane  = tid & 31;
    const int wid   = tid >> 5;
    const int img   = blockIdx.x >> 1;
    const int which = blockIdx.x & 1;     // 0 = fg, 1 = bg
    const int target = (which == 0) ? NPOSMAX : BATCH;
    const unsigned long long* src =
        (which == 0 ? g_fgkeys : g_bgkeys) + img * NPR;

    hist[tid] = 0;
    cand[tid] = ~0ull;
    cand[tid + 1024] = ~0ull;
    if (tid == 0) { misc[0] = 0; misc[1] = NBUCKET - 1; }
    __syncthreads();

    // Pass 1: histogram of valid entries (keys stay in L2)
    for (int i = tid; i < NPR; i += 1024) {
        uint32_t hi = (uint32_t)(src[i] >> 32);
        if (hi < 0x40000000u) {
            float f = __uint_as_float(hi);
            atomicAdd(&hist[(int)(f * (float)NBUCKET)], 1);
        }
    }
    __syncthreads();

    // Hierarchical inclusive scan (2 barriers)
    int v = hist[tid];
#pragma unroll
    for (int off = 1; off < 32; off <<= 1) {
        int o = __shfl_up_sync(0xffffffffu, v, off);
        if (lane >= off) v += o;
    }
    if (lane == 31) wsum[wid] = v;
    __syncthreads();
    if (wid == 0) {
        int w = wsum[lane];
#pragma unroll
        for (int off = 1; off < 32; off <<= 1) {
            int o = __shfl_up_sync(0xffffffffu, w, off);
            if (lane >= off) w += o;
        }
        wsum[lane] = w;
    }
    __syncthreads();
    int incl = v + (wid > 0 ? wsum[wid - 1] : 0);
    cum[tid] = incl;
    __syncthreads();

    const int total = cum[NBUCKET - 1];
    if (incl >= target && (tid == 0 || cum[tid - 1] < target))
        misc[1] = tid;
    __syncthreads();
    const int B = misc[1];

    // Pass 2: compact candidates (buckets <= B)
    for (int i = tid; i < NPR; i += 1024) {
        unsigned long long k = src[i];
        uint32_t hi = (uint32_t)(k >> 32);
        if (hi < 0x40000000u) {
            float f = __uint_as_float(hi);
            if ((int)(f * (float)NBUCKET) <= B) {
                int pos = atomicAdd(&misc[0], 1);
                if (pos < CAND_CAP) cand[pos] = k;
            }
        }
    }
    __syncthreads();
    const int cnt = min(misc[0], CAND_CAP);

    // Adaptive bitonic sort over S = next_pow2(cnt) elements
    int S = 64;
    while (S < cnt) S <<= 1;
    for (int k = 2; k <= S; k <<= 1) {
        for (int j = k >> 1; j > 0; j >>= 1) {
            for (int i = tid; i < S; i += 1024) {
                int ixj = i ^ j;
                if (ixj > i) {
                    bool up = ((i & k) == 0);
                    unsigned long long a = cand[i], b2 = cand[ixj];
                    if ((a > b2) == up) { cand[i] = b2; cand[ixj] = a; }
                }
            }
            __syncthreads();
        }
    }

    // Emit first `target` indices (0-clamped beyond valid count) + total
    if (which == 0) {
        if (tid < NPOSMAX) {
            int idx = (tid < cnt) ? (int)(unsigned)(cand[tid] & 0xffffffffu) : 0;
            g_fginds[img * NPOSMAX + tid] = idx;
        }
    } else {
        if (tid < BATCH) {
            int idx = (tid < cnt) ? (int)(unsigned)(cand[tid] & 0xffffffffu) : 0;
            g_bginds[img * BATCH + tid] = idx;
        }
    }
    if (tid == 0) g_counts[img * 2 + which] = total;
}

// ---------------------------------------------------------------------------
// Kernel 3: assemble outputs.
// Layout: [8*512*8 floats of boxes | 8*512 floats of classes]
// ---------------------------------------------------------------------------
__global__ void gather_kernel(const float* __restrict__ gt,
                              const float* __restrict__ pr,
                              float* __restrict__ out)
{
    const int img  = blockIdx.x;
    const int slot = threadIdx.x;   // 0..511

    const int fgc = g_counts[img * 2 + 0];
    const int bgc = g_counts[img * 2 + 1];
    const int np  = min(fgc, NPOSMAX);
    const int nn  = min(bgc, BATCH - np);

    int sampled;
    if (slot < np) {
        sampled = g_fginds[img * NPOSMAX + min(slot, NPOSMAX - 1)];
    } else {
        sampled = g_bginds[img * BATCH + min(slot - np, BATCH - 1)];
    }
    const bool valid = slot < (np + nn);
    const float v = valid ? 1.0f : 0.0f;

    const int m = g_midx[img * NPR + sampled];
    float4 p = reinterpret_cast<const float4*>(pr)[img * NPR + sampled];
    float4 g = reinterpret_cast<const float4*>(gt)[img * NGT + m];

    float* ob = out + (size_t)(img * BATCH + slot) * 8;
    ob[0] = p.x * v;  ob[1] = p.y * v;  ob[2] = p.z * v;  ob[3] = p.w * v;
    ob[4] = g.x * v;  ob[5] = g.y * v;  ob[6] = g.z * v;  ob[7] = g.w * v;

    const int cls = valid ? g_labels[img * NPR + sampled] : -1;
    out[(size_t)NIMG * BATCH * 8 + img * BATCH + slot] = (float)cls;
}

// ---------------------------------------------------------------------------
// Host: per-image (k1, k2) Threefry keys, partitionable mode:
//   root = key(42) = (0, 42)
//   keys[i]  = TF(root, (0, i))
//   k1, k2   = TF(keys[i], (0,0)), TF(keys[i], (0,1))
// ---------------------------------------------------------------------------
static void compute_keys(ImgKeys& out)
{
    for (int i = 0; i < NIMG; ++i) {
        uint32_t ik0, ik1;
        threefry2x32(0u, 42u, 0u, (uint32_t)i, ik0, ik1);
        uint32_t a0, a1, b0, b1;
        threefry2x32(ik0, ik1, 0u, 0u, a0, a1);   // k1
        threefry2x32(ik0, ik1, 0u, 1u, b0, b1);   // k2
        out.v[i][0] = a0; out.v[i][1] = a1;
        out.v[i][2] = b0; out.v[i][3] = b1;
    }
}

extern "C" void kernel_launch(void* const* d_in, const int* in_sizes, int n_in,
                              void* d_out, int out_size)
{
    const float* gt  = (const float*)d_in[0];  // [8,256,4]
    const int*   gtc = (const int*)  d_in[1];  // [8,256]
    const float* pr  = (const float*)d_in[2];  // [8,8000,4]
    float* out = (float*)d_out;

    (void)in_sizes; (void)n_in; (void)out_size;

    ImgKeys keys;
    compute_keys(keys);

    dim3 g1(NPR / 64, NIMG);               // 125 x 8 blocks, 256 thr each
    match_kernel<<<g1, 256>>>(gt, gtc, pr, keys);
    select_kernel<<<NIMG * 2, 1024>>>();
    gather_kernel<<<NIMG, BATCH>>>(gt, pr, out);
}

// round 6
// speedup vs baseline: 3.1334x; 1.0104x over previous
#include <cuda_runtime.h>
#include <cuda_bf16.h>
#include <cstdint>

// Problem constants
#define NIMG 8
#define NGT  256
#define NPR  8000
#define BATCH 512
#define NPOSMAX 128
#define NBUCKET 1024
#define FG_CAP 512
#define BG_CAP 2048

// ---------------------------------------------------------------------------
// Threefry-2x32 (JAX default PRNG), 20 rounds.
// ---------------------------------------------------------------------------
__host__ __device__ __forceinline__ void threefry2x32(
    uint32_t k0, uint32_t k1, uint32_t x0, uint32_t x1,
    uint32_t& o0, uint32_t& o1)
{
    uint32_t ks0 = k0, ks1 = k1, ks2 = k0 ^ k1 ^ 0x1BD11BDAu;
    uint32_t a = x0 + ks0, b = x1 + ks1;
    const uint32_t rot[2][4] = {{13u,15u,26u,6u},{17u,29u,16u,24u}};
#pragma unroll
    for (int i = 0; i < 5; ++i) {
        const uint32_t* r = rot[i & 1];
#pragma unroll
        for (int q = 0; q < 4; ++q) {
            a += b;
            b = (b << r[q]) | (b >> (32u - r[q]));
            b ^= a;
        }
        uint32_t i1 = (uint32_t)(i + 1);
        uint32_t kA = (i % 3 == 0) ? ks1 : (i % 3 == 1) ? ks2 : ks0;
        uint32_t kB = (i % 3 == 0) ? ks2 : (i % 3 == 1) ? ks0 : ks1;
        a += kA;
        b += kB + i1;
    }
    o0 = a; o1 = b;
}

__host__ __device__ __forceinline__ float jax_uniform_from_bits(uint32_t bits) {
    uint32_t fb = (bits >> 9) | 0x3f800000u;
    float f;
#ifdef __CUDA_ARCH__
    f = __uint_as_float(fb);
#else
    union { uint32_t u; float f; } c; c.u = fb; f = c.f;
#endif
    return f - 1.0f;
}

struct ImgKeys {
    uint32_t v[NIMG][4];   // per image: k1 (2 words), k2 (2 words)
};

// ---------------------------------------------------------------------------
// Scratch (device globals — no allocation allowed)
// ---------------------------------------------------------------------------
__device__ int                g_midx[NIMG * NPR];
__device__ int                g_labels[NIMG * NPR];
__device__ unsigned long long g_fgkeys[NIMG * NPR];
__device__ unsigned long long g_bgkeys[NIMG * NPR];

// ---------------------------------------------------------------------------
// Kernel 1: IoU matching + labels + PRNG sort keys.
// 4 threads per proposal; thread `sub` handles GT subset m = sub, sub+4, ...
// First eval peeled (one exact division) so the loop invariant is best >= 0,
// collapsing the division-avoidance guard to a single test:
//   inter <= __fmul_rd(best, uni) <= best*uni  =>  q <= best
//   => rn(q) <= best  => strict '>' update impossible  => safe to skip.
// All computed iou values are bit-identical to the reference path.
// ---------------------------------------------------------------------------
__global__ void match_kernel(const float* __restrict__ gt,
                             const int*   __restrict__ gtc,
                             const float* __restrict__ pr,
                             ImgKeys keys)
{
    const int img = blockIdx.y;
    const int tid = threadIdx.x;           // 256 threads = 64 proposals x 4
    const int sub = tid & 3;
    const int r   = blockIdx.x * 64 + (tid >> 2);   // 8000/64 = 125 blocks

    __shared__ float4 sgt[NGT];
    __shared__ float  sag[NGT];
    __shared__ int    sgc[NGT];

    {
        float4 g = reinterpret_cast<const float4*>(gt)[img * NGT + tid];
        sgt[tid] = g;
        sag[tid] = __fmul_rn(__fsub_rn(g.z, g.x), __fsub_rn(g.w, g.y));
        sgc[tid] = gtc[img * NGT + tid];
    }
    __syncthreads();

    float4 p = reinterpret_cast<const float4*>(pr)[img * NPR + r];
    const float ap = __fmul_rn(__fsub_rn(p.z, p.x), __fsub_rn(p.w, p.y));

    // Peeled first eval (m = sub): unconditional exact division
    float best;
    int   bi = sub;
    {
        float4 g = sgt[sub];
        float wx = fmaxf(__fsub_rn(fminf(g.z, p.z), fmaxf(g.x, p.x)), 0.0f);
        float wy = fmaxf(__fsub_rn(fminf(g.w, p.w), fmaxf(g.y, p.y)), 0.0f);
        float inter = __fmul_rn(wx, wy);
        float uni   = __fsub_rn(__fadd_rn(sag[sub], ap), inter);
        best = __fdiv_rn(inter, uni);
    }

#pragma unroll 9
    for (int i = 1; i < NGT / 4; ++i) {
        const int m = sub + 4 * i;
        float4 g = sgt[m];
        float wx = fmaxf(__fsub_rn(fminf(g.z, p.z), fmaxf(g.x, p.x)), 0.0f);
        float wy = fmaxf(__fsub_rn(fminf(g.w, p.w), fmaxf(g.y, p.y)), 0.0f);
        float inter = __fmul_rn(wx, wy);
        float uni   = __fsub_rn(__fadd_rn(sag[m], ap), inter);
        if (inter > __fmul_rd(best, uni)) {
            float iou = __fdiv_rn(inter, uni);
            if (iou > best) { best = iou; bi = m; }   // first-max tie-break
        }
    }

    // Reduce across the 4 subs (groups of 4 lanes are xor-1/2 closed)
#pragma unroll
    for (int off = 1; off <= 2; off <<= 1) {
        float ob = __shfl_xor_sync(0xffffffffu, best, off);
        int  obi = __shfl_xor_sync(0xffffffffu, bi,   off);
        if (ob > best || (ob == best && obi < bi)) { best = ob; bi = obi; }
    }

    const bool fg = (best >= 0.5f);        // FG_IOU == BG_IOU == 0.5

    // One converged Threefry per lane: subs 0/1 use k1, subs 2/3 use k2.
    const uint32_t* kv = keys.v[img];
    uint32_t kk0 = (sub & 2) ? kv[2] : kv[0];
    uint32_t kk1 = (sub & 2) ? kv[3] : kv[1];
    uint32_t w0, w1;
    threefry2x32(kk0, kk1, 0u, (uint32_t)r, w0, w1);
    float u = jax_uniform_from_bits(w0 ^ w1);

    const unsigned long long INVALID = (0x40000000ull << 32) | (unsigned)r;
    unsigned long long keyv =
        (((unsigned long long)__float_as_uint(u)) << 32) | (unsigned)r;

    if (sub == 0) g_fgkeys[img * NPR + r] = fg ? keyv : INVALID;
    if (sub == 2) g_bgkeys[img * NPR + r] = fg ? INVALID : keyv;
    if (sub == 1) g_midx[img * NPR + r] = bi;
    if (sub == 3) g_labels[img * NPR + r] = fg ? sgc[bi] : 0;
}

// ---------------------------------------------------------------------------
// Kernel 2 (fused): per-image selection of fg/bg pools CONCURRENTLY
// (warps 0-15 = fg, warps 16-31 = bg, synchronized with named barriers),
// followed by the gather/epilogue from SMEM. One block per image.
//
// Selection per half: histogram of uniform scores into 1024 buckets
// (bucket = floor(u*1024), monotone in u -> candidates with bucket <= B,
// where cum[B] >= target, are a superset of the bottom-target keys),
// compaction, then adaptive bitonic sort of the u64 (score,index) keys
// -> exact stable-argsort prefix.
// ---------------------------------------------------------------------------
#define NB() asm volatile("bar.sync %0, %1;" :: "r"(half + 1), "r"(512) : "memory")

__global__ void select_gather_kernel(const float* __restrict__ gt,
                                     const float* __restrict__ pr,
                                     float* __restrict__ out)
{
    __shared__ unsigned long long cand_fg[FG_CAP];
    __shared__ unsigned long long cand_bg[BG_CAP];
    __shared__ int hist2[2][NBUCKET];
    __shared__ int cum2[2][NBUCKET];
    __shared__ int wsum2[2][16];
    __shared__ int miscs[2][2];    // [h][0] = cnt, [h][1] = B
    __shared__ int totals[2];

    const int img  = blockIdx.x;
    const int tid  = threadIdx.x;  // 1024
    const int half = tid >> 9;     // 0 = fg, 1 = bg
    const int ht   = tid & 511;
    const int lane = tid & 31;
    const int hw   = ht >> 5;      // warp within half, 0..15

    const int target = half ? BATCH : NPOSMAX;
    const int cap    = half ? BG_CAP : FG_CAP;
    unsigned long long* cand = half ? cand_bg : cand_fg;
    const unsigned long long* src = (half ? g_bgkeys : g_fgkeys) + img * NPR;

    hist2[half][2 * ht]     = 0;
    hist2[half][2 * ht + 1] = 0;
    for (int i = ht; i < cap; i += 512) cand[i] = ~0ull;
    if (ht == 0) { miscs[half][0] = 0; miscs[half][1] = NBUCKET - 1; }
    NB();

    // Pass 1: histogram of valid entries
    for (int i = ht; i < NPR; i += 512) {
        uint32_t hi = (uint32_t)(src[i] >> 32);
        if (hi < 0x40000000u)
            atomicAdd(&hist2[half][(int)(__uint_as_float(hi) * (float)NBUCKET)], 1);
    }
    NB();

    // Inclusive scan of 1024 buckets with 512 threads (pairs per thread)
    int v0 = hist2[half][2 * ht];
    int v1 = hist2[half][2 * ht + 1];
    int v  = v0 + v1;
#pragma unroll
    for (int off = 1; off < 32; off <<= 1) {
        int o = __shfl_up_sync(0xffffffffu, v, off);
        if (lane >= off) v += o;
    }
    if (lane == 31) wsum2[half][hw] = v;
    NB();
    if (ht < 32) {
        int w = (lane < 16) ? wsum2[half][lane] : 0;
#pragma unroll
        for (int off = 1; off < 32; off <<= 1) {
            int o = __shfl_up_sync(0xffffffffu, w, off);
            if (lane >= off) w += o;
        }
        if (lane < 16) wsum2[half][lane] = w;
    }
    NB();
    int incl = v + (hw ? wsum2[half][hw - 1] : 0);
    cum2[half][2 * ht]     = incl - v1;
    cum2[half][2 * ht + 1] = incl;
    NB();

    if (ht == 0) totals[half] = cum2[half][NBUCKET - 1];
#pragma unroll
    for (int e = 0; e < 2; ++e) {
        int b  = 2 * ht + e;
        int c  = cum2[half][b];
        int pv = b ? cum2[half][b - 1] : 0;
        if (c >= target && pv < target) miscs[half][1] = b;   // unique writer
    }
    NB();
    const int B = miscs[half][1];

    // Pass 2: compact candidates (buckets <= B)
    for (int i = ht; i < NPR; i += 512) {
        unsigned long long k = src[i];
        uint32_t hi = (uint32_t)(k >> 32);
        if (hi < 0x40000000u) {
            if ((int)(__uint_as_float(hi) * (float)NBUCKET) <= B) {
                int pos = atomicAdd(&miscs[half][0], 1);
                if (pos < cap) cand[pos] = k;
            }
        }
    }
    NB();
    const int cnt = min(miscs[half][0], cap);

    // Adaptive bitonic sort over S = next_pow2(cnt), 512 threads per half
    int S = 64;
    while (S < cnt) S <<= 1;
    for (int k = 2; k <= S; k <<= 1) {
        for (int j = k >> 1; j > 0; j >>= 1) {
            for (int i = ht; i < S; i += 512) {
                int ixj = i ^ j;
                if (ixj > i) {
                    bool up = ((i & k) == 0);
                    unsigned long long a = cand[i], b2 = cand[ixj];
                    if ((a > b2) == up) { cand[i] = b2; cand[ixj] = a; }
                }
            }
            NB();
        }
    }

    __syncthreads();   // join fg & bg halves

    // Gather / epilogue straight out of SMEM
    if (tid < BATCH) {
        const int slot = tid;
        const int np = min(totals[0], NPOSMAX);
        const int nn = min(totals[1], BATCH - np);
        const bool valid = slot < (np + nn);

        int sampled = 0;
        if (slot < np)   sampled = (int)(unsigned)(cand_fg[slot] & 0xffffffffu);
        else if (valid)  sampled = (int)(unsigned)(cand_bg[slot - np] & 0xffffffffu);

        const float vmul = valid ? 1.0f : 0.0f;
        const int m = g_midx[img * NPR + sampled];
        float4 p = reinterpret_cast<const float4*>(pr)[img * NPR + sampled];
        float4 g = reinterpret_cast<const float4*>(gt)[img * NGT + m];

        float* ob = out + (size_t)(img * BATCH + slot) * 8;
        ob[0] = p.x * vmul;  ob[1] = p.y * vmul;
        ob[2] = p.z * vmul;  ob[3] = p.w * vmul;
        ob[4] = g.x * vmul;  ob[5] = g.y * vmul;
        ob[6] = g.z * vmul;  ob[7] = g.w * vmul;

        const int cls = valid ? g_labels[img * NPR + sampled] : -1;
        out[(size_t)NIMG * BATCH * 8 + img * BATCH + slot] = (float)cls;
    }
}

// ---------------------------------------------------------------------------
// Host: per-image (k1, k2) Threefry keys, partitionable mode:
//   root = key(42) = (0, 42)
//   keys[i]  = TF(root, (0, i))
//   k1, k2   = TF(keys[i], (0,0)), TF(keys[i], (0,1))
// ---------------------------------------------------------------------------
static void compute_keys(ImgKeys& out)
{
    for (int i = 0; i < NIMG; ++i) {
        uint32_t ik0, ik1;
        threefry2x32(0u, 42u, 0u, (uint32_t)i, ik0, ik1);
        uint32_t a0, a1, b0, b1;
        threefry2x32(ik0, ik1, 0u, 0u, a0, a1);   // k1
        threefry2x32(ik0, ik1, 0u, 1u, b0, b1);   // k2
        out.v[i][0] = a0; out.v[i][1] = a1;
        out.v[i][2] = b0; out.v[i][3] = b1;
    }
}

extern "C" void kernel_launch(void* const* d_in, const int* in_sizes, int n_in,
                              void* d_out, int out_size)
{
    const float* gt  = (const float*)d_in[0];  // [8,256,4]
    const int*   gtc = (const int*)  d_in[1];  // [8,256]
    const float* pr  = (const float*)d_in[2];  // [8,8000,4]
    float* out = (float*)d_out;

    (void)in_sizes; (void)n_in; (void)out_size;

    ImgKeys keys;
    compute_keys(keys);

    dim3 g1(NPR / 64, NIMG);               // 125 x 8 blocks, 256 thr each
    match_kernel<<<g1, 256>>>(gt, gtc, pr, keys);
    select_gather_kernel<<<NIMG, 1024>>>(gt, pr, out);
}

// round 7
// speedup vs baseline: 3.9346x; 1.2557x over previous
#include <cuda_runtime.h>
#include <cuda_bf16.h>
#include <cstdint>

// Problem constants
#define NIMG 8
#define NGT  256
#define NPR  8000
#define BATCH 512
#define NPOSMAX 128
#define NBUCKET 1024
#define FG_CAP 512
#define BG_CAP 1024

// ---------------------------------------------------------------------------
// Threefry-2x32 (JAX default PRNG), 20 rounds.
// ---------------------------------------------------------------------------
__host__ __device__ __forceinline__ void threefry2x32(
    uint32_t k0, uint32_t k1, uint32_t x0, uint32_t x1,
    uint32_t& o0, uint32_t& o1)
{
    uint32_t ks0 = k0, ks1 = k1, ks2 = k0 ^ k1 ^ 0x1BD11BDAu;
    uint32_t a = x0 + ks0, b = x1 + ks1;
    const uint32_t rot[2][4] = {{13u,15u,26u,6u},{17u,29u,16u,24u}};
#pragma unroll
    for (int i = 0; i < 5; ++i) {
        const uint32_t* r = rot[i & 1];
#pragma unroll
        for (int q = 0; q < 4; ++q) {
            a += b;
            b = (b << r[q]) | (b >> (32u - r[q]));
            b ^= a;
        }
        uint32_t i1 = (uint32_t)(i + 1);
        uint32_t kA = (i % 3 == 0) ? ks1 : (i % 3 == 1) ? ks2 : ks0;
        uint32_t kB = (i % 3 == 0) ? ks2 : (i % 3 == 1) ? ks0 : ks1;
        a += kA;
        b += kB + i1;
    }
    o0 = a; o1 = b;
}

__host__ __device__ __forceinline__ float jax_uniform_from_bits(uint32_t bits) {
    uint32_t fb = (bits >> 9) | 0x3f800000u;
    float f;
#ifdef __CUDA_ARCH__
    f = __uint_as_float(fb);
#else
    union { uint32_t u; float f; } c; c.u = fb; f = c.f;
#endif
    return f - 1.0f;
}

struct ImgKeys {
    uint32_t v[NIMG][4];   // per image: k1 (2 words), k2 (2 words)
};

// ---------------------------------------------------------------------------
// Scratch (device globals — no allocation allowed)
// ---------------------------------------------------------------------------
__device__ int                g_midx[NIMG * NPR];
__device__ int                g_labels[NIMG * NPR];
__device__ unsigned long long g_fgkeys[NIMG * NPR];
__device__ unsigned long long g_bgkeys[NIMG * NPR];

// ---------------------------------------------------------------------------
// Kernel 1: IoU matching + labels + PRNG sort keys.
// 4 threads per proposal-pair lane-group; thread `sub` handles GT subset
// m = sub, sub+4, ... for TWO proposals (r0, r1 = r0+64), amortizing the
// SMEM loads and loop overhead. First eval peeled (one exact division) so the
// loop invariant is best >= 0, collapsing division-avoidance to one test:
//   inter <= __fmul_rd(best, uni) <= best*uni  =>  rn(inter/uni) <= best
//   => strict '>' update impossible => safe to skip.  Bit-identical to ref.
// ---------------------------------------------------------------------------
__global__ void match_kernel(const float* __restrict__ gt,
                             const int*   __restrict__ gtc,
                             const float* __restrict__ pr,
                             ImgKeys keys)
{
    const int img = blockIdx.y;
    const int tid = threadIdx.x;           // 256 threads = 64 pairs x 4 subs
    const int sub = tid & 3;
    const int pid = tid >> 2;              // 0..63
    const int base = blockIdx.x * 128;     // 63 blocks cover 8064 >= 8000
    const int r0 = base + pid;
    const int r1 = base + 64 + pid;
    const bool has1 = (r1 < NPR);
    const int r1c = has1 ? r1 : (NPR - 1);

    __shared__ float4 sgt[NGT];
    __shared__ float  sag[NGT];
    __shared__ int    sgc[NGT];

    {
        float4 g = reinterpret_cast<const float4*>(gt)[img * NGT + tid];
        sgt[tid] = g;
        sag[tid] = __fmul_rn(__fsub_rn(g.z, g.x), __fsub_rn(g.w, g.y));
        sgc[tid] = gtc[img * NGT + tid];
    }
    __syncthreads();

    float4 p0 = reinterpret_cast<const float4*>(pr)[img * NPR + r0];
    float4 p1 = reinterpret_cast<const float4*>(pr)[img * NPR + r1c];
    const float ap0 = __fmul_rn(__fsub_rn(p0.z, p0.x), __fsub_rn(p0.w, p0.y));
    const float ap1 = __fmul_rn(__fsub_rn(p1.z, p1.x), __fsub_rn(p1.w, p1.y));

    float best0, best1;
    int   bi0 = sub, bi1 = sub;
    {   // peeled first eval (m = sub): unconditional exact division
        float4 g = sgt[sub];
        float ag = sag[sub];
        float wx0 = fmaxf(__fsub_rn(fminf(g.z, p0.z), fmaxf(g.x, p0.x)), 0.0f);
        float wy0 = fmaxf(__fsub_rn(fminf(g.w, p0.w), fmaxf(g.y, p0.y)), 0.0f);
        float in0 = __fmul_rn(wx0, wy0);
        best0 = __fdiv_rn(in0, __fsub_rn(__fadd_rn(ag, ap0), in0));
        float wx1 = fmaxf(__fsub_rn(fminf(g.z, p1.z), fmaxf(g.x, p1.x)), 0.0f);
        float wy1 = fmaxf(__fsub_rn(fminf(g.w, p1.w), fmaxf(g.y, p1.y)), 0.0f);
        float in1 = __fmul_rn(wx1, wy1);
        best1 = __fdiv_rn(in1, __fsub_rn(__fadd_rn(ag, ap1), in1));
    }

#pragma unroll 9
    for (int i = 1; i < NGT / 4; ++i) {
        const int m = sub + 4 * i;
        float4 g = sgt[m];
        float ag = sag[m];

        float wx0 = fmaxf(__fsub_rn(fminf(g.z, p0.z), fmaxf(g.x, p0.x)), 0.0f);
        float wy0 = fmaxf(__fsub_rn(fminf(g.w, p0.w), fmaxf(g.y, p0.y)), 0.0f);
        float in0 = __fmul_rn(wx0, wy0);
        float un0 = __fsub_rn(__fadd_rn(ag, ap0), in0);
        if (in0 > __fmul_rd(best0, un0)) {
            float iou = __fdiv_rn(in0, un0);
            if (iou > best0) { best0 = iou; bi0 = m; }
        }

        float wx1 = fmaxf(__fsub_rn(fminf(g.z, p1.z), fmaxf(g.x, p1.x)), 0.0f);
        float wy1 = fmaxf(__fsub_rn(fminf(g.w, p1.w), fmaxf(g.y, p1.y)), 0.0f);
        float in1 = __fmul_rn(wx1, wy1);
        float un1 = __fsub_rn(__fadd_rn(ag, ap1), in1);
        if (in1 > __fmul_rd(best1, un1)) {
            float iou = __fdiv_rn(in1, un1);
            if (iou > best1) { best1 = iou; bi1 = m; }
        }
    }

    // Reduce across the 4 subs: (max value, min index) == sequential first-max
#pragma unroll
    for (int off = 1; off <= 2; off <<= 1) {
        float ob = __shfl_xor_sync(0xffffffffu, best0, off);
        int  obi = __shfl_xor_sync(0xffffffffu, bi0,   off);
        if (ob > best0 || (ob == best0 && obi < bi0)) { best0 = ob; bi0 = obi; }
        ob  = __shfl_xor_sync(0xffffffffu, best1, off);
        obi = __shfl_xor_sync(0xffffffffu, bi1,   off);
        if (ob > best1 || (ob == best1 && obi < bi1)) { best1 = ob; bi1 = obi; }
    }

    const bool fg0 = (best0 >= 0.5f);      // FG_IOU == BG_IOU == 0.5
    const bool fg1 = (best1 >= 0.5f);

    // One converged Threefry per lane:
    //   sub0 -> (k1, r0), sub1 -> (k1, r1), sub2 -> (k2, r0), sub3 -> (k2, r1)
    const uint32_t* kv = keys.v[img];
    uint32_t kk0 = (sub & 2) ? kv[2] : kv[0];
    uint32_t kk1 = (sub & 2) ? kv[3] : kv[1];
    uint32_t rr  = (sub & 1) ? (uint32_t)r1c : (uint32_t)r0;
    uint32_t w0, w1;
    threefry2x32(kk0, kk1, 0u, rr, w0, w1);
    float u = jax_uniform_from_bits(w0 ^ w1);
    float uo = __shfl_xor_sync(0xffffffffu, u, 1);
    float uA = (sub & 1) ? uo : u;     // for r0 (this sub-pair's key)
    float uB = (sub & 1) ? u  : uo;    // for r1

    const unsigned long long INV0 = (0x40000000ull << 32) | (unsigned)r0;
    const unsigned long long INV1 = (0x40000000ull << 32) | (unsigned)r1;
    unsigned long long key0 =
        (((unsigned long long)__float_as_uint(uA)) << 32) | (unsigned)r0;
    unsigned long long key1 =
        (((unsigned long long)__float_as_uint(uB)) << 32) | (unsigned)r1;

    const size_t ib = (size_t)img * NPR;
    if (sub == 0) {
        g_fgkeys[ib + r0] = fg0 ? key0 : INV0;
        if (has1) g_fgkeys[ib + r1] = fg1 ? key1 : INV1;
    } else if (sub == 2) {
        g_bgkeys[ib + r0] = fg0 ? INV0 : key0;
        if (has1) g_bgkeys[ib + r1] = fg1 ? INV1 : key1;
    } else if (sub == 1) {
        g_midx[ib + r0] = bi0;
        if (has1) g_midx[ib + r1] = bi1;
    } else {
        g_labels[ib + r0] = fg0 ? sgc[bi0] : 0;
        if (has1) g_labels[ib + r1] = fg1 ? sgc[bi1] : 0;
    }
}

// ---------------------------------------------------------------------------
// Kernel 2 (fused, SORT-FREE): per-image fg/bg selection CONCURRENTLY
// (warps 0-15 = fg, warps 16-31 = bg, named barriers), then gather from SMEM.
//
// Selection = exact stable-argsort prefix without sorting:
//  1. histogram of u into 1024 buckets (bucket = floor(u*1024), monotone)
//  2. prefix sums -> cumE[] (exclusive), threshold bucket B (cum >= target)
//  3. compact candidates with bucket <= B, grouped by bucket via atomic
//     per-bucket offsets
//  4. exact rank of each candidate = cumE[bucket] + #(same-bucket keys < k)
//     (keys are unique u64 (score,index) -> total order -> rank bijection);
//     rank < target scatter-writes the index into the sorted slot directly.
// ---------------------------------------------------------------------------
#define NB() asm volatile("bar.sync %0, %1;" :: "r"(half + 1), "r"(512) : "memory")

__global__ void select_gather_kernel(const float* __restrict__ gt,
                                     const float* __restrict__ pr,
                                     float* __restrict__ out)
{
    __shared__ unsigned long long cand_fg[FG_CAP];
    __shared__ unsigned long long cand_bg[BG_CAP];
    __shared__ int cumE2[2][NBUCKET + 1];  // exclusive cum (static)
    __shared__ int off2[2][NBUCKET];       // mutable bucket write cursors
    __shared__ int wsum2[2][16];
    __shared__ int bidx[2];
    __shared__ int totals[2];
    __shared__ int sfg[NPOSMAX];
    __shared__ int sbg[BATCH];

    const int img  = blockIdx.x;
    const int tid  = threadIdx.x;  // 1024
    const int half = tid >> 9;     // 0 = fg, 1 = bg
    const int ht   = tid & 511;
    const int lane = tid & 31;
    const int hw   = ht >> 5;      // warp within half, 0..15

    const int target = half ? BATCH : NPOSMAX;
    const int cap    = half ? BG_CAP : FG_CAP;
    unsigned long long* cand = half ? cand_bg : cand_fg;
    const unsigned long long* src = (half ? g_bgkeys : g_fgkeys)
                                    + (size_t)img * NPR;

    // Phase 0: zero histogram (off2 doubles as hist), init bidx
    off2[half][2 * ht]     = 0;
    off2[half][2 * ht + 1] = 0;
    if (ht == 0) bidx[half] = NBUCKET - 1;
    NB();

    // Phase 1: histogram of valid entries
    for (int i = ht; i < NPR; i += 512) {
        uint32_t hi = (uint32_t)(src[i] >> 32);
        if (hi < 0x40000000u)
            atomicAdd(&off2[half][(int)(__uint_as_float(hi) * (float)NBUCKET)], 1);
    }
    NB();

    // Phase 2: scan (each thread owns buckets 2ht, 2ht+1)
    const int v0 = off2[half][2 * ht];
    const int v1 = off2[half][2 * ht + 1];
    int v = v0 + v1;
#pragma unroll
    for (int off = 1; off < 32; off <<= 1) {
        int o = __shfl_up_sync(0xffffffffu, v, off);
        if (lane >= off) v += o;
    }
    if (lane == 31) wsum2[half][hw] = v;
    NB();
    if (ht < 32) {
        int w = (lane < 16) ? wsum2[half][lane] : 0;
#pragma unroll
        for (int off = 1; off < 32; off <<= 1) {
            int o = __shfl_up_sync(0xffffffffu, w, off);
            if (lane >= off) w += o;
        }
        if (lane < 16) wsum2[half][lane] = w;
    }
    NB();
    const int incl  = v + (hw ? wsum2[half][hw - 1] : 0);  // incl cum @ 2ht+1
    const int excl1 = incl - v1;                            // excl cum @ 2ht+1
    const int excl0 = excl1 - v0;                           // excl cum @ 2ht
    cumE2[half][2 * ht]     = excl0;
    cumE2[half][2 * ht + 1] = excl1;
    off2[half][2 * ht]      = excl0;
    off2[half][2 * ht + 1]  = excl1;
    if (ht == 511) { cumE2[half][NBUCKET] = incl; totals[half] = incl; }
    // threshold bucket: unique b with excl < target <= incl
    if (excl0 < target && excl0 + v0 >= target) bidx[half] = 2 * ht;
    if (excl1 < target && incl >= target)       bidx[half] = 2 * ht + 1;
    NB();
    const int B = bidx[half];

    // Phase 3: compact candidates (bucket <= B), grouped by bucket
    for (int i = ht; i < NPR; i += 512) {
        unsigned long long k = src[i];
        uint32_t hi = (uint32_t)(k >> 32);
        if (hi < 0x40000000u) {
            int b = (int)(__uint_as_float(hi) * (float)NBUCKET);
            if (b <= B) {
                int pos = atomicAdd(&off2[half][b], 1);
                if (pos < cap) cand[pos] = k;
            }
        }
    }
    NB();
    const int cnt = min(cumE2[half][B + 1], cap);

    // Phase 4: exact rank + scatter into sorted slots
    int* inds = half ? sbg : sfg;
    for (int i = ht; i < cnt; i += 512) {
        unsigned long long k = cand[i];
        int b  = (int)(__uint_as_float((uint32_t)(k >> 32)) * (float)NBUCKET);
        int lo = cumE2[half][b];
        int hiE = min(cumE2[half][b + 1], cnt);
        int rank = lo;
        for (int j = lo; j < hiE; ++j)
            rank += (cand[j] < k);
        if (rank < target) inds[rank] = (int)(unsigned)(k & 0xffffffffu);
    }
    __syncthreads();   // join fg & bg halves

    // Gather / epilogue straight out of SMEM
    if (tid < BATCH) {
        const int slot = tid;
        const int np = min(totals[0], NPOSMAX);
        const int nn = min(totals[1], BATCH - np);
        const bool valid = slot < (np + nn);

        int sampled = 0;
        if (slot < np)   sampled = sfg[slot];
        else if (valid)  sampled = sbg[slot - np];

        const float vmul = valid ? 1.0f : 0.0f;
        const int m = g_midx[(size_t)img * NPR + sampled];
        float4 p = reinterpret_cast<const float4*>(pr)[img * NPR + sampled];
        float4 g = reinterpret_cast<const float4*>(gt)[img * NGT + m];

        float* ob = out + (size_t)(img * BATCH + slot) * 8;
        ob[0] = p.x * vmul;  ob[1] = p.y * vmul;
        ob[2] = p.z * vmul;  ob[3] = p.w * vmul;
        ob[4] = g.x * vmul;  ob[5] = g.y * vmul;
        ob[6] = g.z * vmul;  ob[7] = g.w * vmul;

        const int cls = valid ? g_labels[(size_t)img * NPR + sampled] : -1;
        out[(size_t)NIMG * BATCH * 8 + img * BATCH + slot] = (float)cls;
    }
}

// ---------------------------------------------------------------------------
// Host: per-image (k1, k2) Threefry keys, partitionable mode:
//   root = key(42) = (0, 42)
//   keys[i]  = TF(root, (0, i))
//   k1, k2   = TF(keys[i], (0,0)), TF(keys[i], (0,1))
// ---------------------------------------------------------------------------
static void compute_keys(ImgKeys& out)
{
    for (int i = 0; i < NIMG; ++i) {
        uint32_t ik0, ik1;
        threefry2x32(0u, 42u, 0u, (uint32_t)i, ik0, ik1);
        uint32_t a0, a1, b0, b1;
        threefry2x32(ik0, ik1, 0u, 0u, a0, a1);   // k1
        threefry2x32(ik0, ik1, 0u, 1u, b0, b1);   // k2
        out.v[i][0] = a0; out.v[i][1] = a1;
        out.v[i][2] = b0; out.v[i][3] = b1;
    }
}

extern "C" void kernel_launch(void* const* d_in, const int* in_sizes, int n_in,
                              void* d_out, int out_size)
{
    const float* gt  = (const float*)d_in[0];  // [8,256,4]
    const int*   gtc = (const int*)  d_in[1];  // [8,256]
    const float* pr  = (const float*)d_in[2];  // [8,8000,4]
    float* out = (float*)d_out;

    (void)in_sizes; (void)n_in; (void)out_size;

    ImgKeys keys;
    compute_keys(keys);

    dim3 g1((NPR + 127) / 128, NIMG);      // 63 x 8 blocks, 256 thr each
    match_kernel<<<g1, 256>>>(gt, gtc, pr, keys);
    select_gather_kernel<<<NIMG, 1024>>>(gt, pr, out);
}

// round 8
// speedup vs baseline: 4.2246x; 1.0737x over previous
#include <cuda_runtime.h>
#include <cuda_bf16.h>
#include <cstdint>

// Problem constants
#define NIMG 8
#define NGT  256
#define NPR  8000
#define BATCH 512
#define NPOSMAX 128
#define NBUCKET 1024
#define FG_CAP 512
#define BG_CAP 1024

// ---------------------------------------------------------------------------
// Threefry-2x32 (JAX default PRNG), 20 rounds.
// ---------------------------------------------------------------------------
__host__ __device__ __forceinline__ void threefry2x32(
    uint32_t k0, uint32_t k1, uint32_t x0, uint32_t x1,
    uint32_t& o0, uint32_t& o1)
{
    uint32_t ks0 = k0, ks1 = k1, ks2 = k0 ^ k1 ^ 0x1BD11BDAu;
    uint32_t a = x0 + ks0, b = x1 + ks1;
    const uint32_t rot[2][4] = {{13u,15u,26u,6u},{17u,29u,16u,24u}};
#pragma unroll
    for (int i = 0; i < 5; ++i) {
        const uint32_t* r = rot[i & 1];
#pragma unroll
        for (int q = 0; q < 4; ++q) {
            a += b;
            b = (b << r[q]) | (b >> (32u - r[q]));
            b ^= a;
        }
        uint32_t i1 = (uint32_t)(i + 1);
        uint32_t kA = (i % 3 == 0) ? ks1 : (i % 3 == 1) ? ks2 : ks0;
        uint32_t kB = (i % 3 == 0) ? ks2 : (i % 3 == 1) ? ks0 : ks1;
        a += kA;
        b += kB + i1;
    }
    o0 = a; o1 = b;
}

__host__ __device__ __forceinline__ float jax_uniform_from_bits(uint32_t bits) {
    uint32_t fb = (bits >> 9) | 0x3f800000u;
    float f;
#ifdef __CUDA_ARCH__
    f = __uint_as_float(fb);
#else
    union { uint32_t u; float f; } c; c.u = fb; f = c.f;
#endif
    return f - 1.0f;
}

struct ImgKeys {
    uint32_t v[NIMG][4];   // per image: k1 (2 words), k2 (2 words)
};

// ---------------------------------------------------------------------------
// Scratch (device globals — no allocation allowed).
// g_hist is all-zeros at module load; select_gather_kernel restores it to
// zeros every call, so every kernel_launch sees the identical initial state.
// ---------------------------------------------------------------------------
__device__ int                g_midx[NIMG * NPR];
__device__ int                g_labels[NIMG * NPR];
__device__ unsigned long long g_fgkeys[NIMG * NPR];
__device__ unsigned long long g_bgkeys[NIMG * NPR];
__device__ int                g_hist[NIMG * 2 * NBUCKET];

// ---------------------------------------------------------------------------
// Kernel 1: IoU matching + labels + PRNG sort keys + bucket histogram.
// 4 threads per proposal-pair lane-group; thread `sub` handles GT subset
// m = sub, sub+4, ... for TWO proposals (r0, r1 = r0+64). First eval peeled
// (one exact division) so the loop invariant is best >= 0, collapsing
// division-avoidance to one test:
//   inter <= __fmul_rd(best, uni) <= best*uni  =>  rn(inter/uni) <= best
//   => strict '>' update impossible => safe to skip.  Bit-identical to ref.
// Each proposal contributes exactly one histogram entry (fg pool if
// best >= 0.5, else bg pool), bucket = (int)(u * 1024) with the same float
// expression used in the select kernel.
// ---------------------------------------------------------------------------
__global__ void match_kernel(const float* __restrict__ gt,
                             const int*   __restrict__ gtc,
                             const float* __restrict__ pr,
                             ImgKeys keys)
{
    const int img = blockIdx.y;
    const int tid = threadIdx.x;           // 256 threads = 64 pairs x 4 subs
    const int sub = tid & 3;
    const int pid = tid >> 2;              // 0..63
    const int base = blockIdx.x * 128;     // 63 blocks cover 8064 >= 8000
    const int r0 = base + pid;
    const int r1 = base + 64 + pid;
    const bool has1 = (r1 < NPR);
    const int r1c = has1 ? r1 : (NPR - 1);

    __shared__ float4 sgt[NGT];
    __shared__ float  sag[NGT];
    __shared__ int    sgc[NGT];

    {
        float4 g = reinterpret_cast<const float4*>(gt)[img * NGT + tid];
        sgt[tid] = g;
        sag[tid] = __fmul_rn(__fsub_rn(g.z, g.x), __fsub_rn(g.w, g.y));
        sgc[tid] = gtc[img * NGT + tid];
    }
    __syncthreads();

    float4 p0 = reinterpret_cast<const float4*>(pr)[img * NPR + r0];
    float4 p1 = reinterpret_cast<const float4*>(pr)[img * NPR + r1c];
    const float ap0 = __fmul_rn(__fsub_rn(p0.z, p0.x), __fsub_rn(p0.w, p0.y));
    const float ap1 = __fmul_rn(__fsub_rn(p1.z, p1.x), __fsub_rn(p1.w, p1.y));

    float best0, best1;
    int   bi0 = sub, bi1 = sub;
    {   // peeled first eval (m = sub): unconditional exact division
        float4 g = sgt[sub];
        float ag = sag[sub];
        float wx0 = fmaxf(__fsub_rn(fminf(g.z, p0.z), fmaxf(g.x, p0.x)), 0.0f);
        float wy0 = fmaxf(__fsub_rn(fminf(g.w, p0.w), fmaxf(g.y, p0.y)), 0.0f);
        float in0 = __fmul_rn(wx0, wy0);
        best0 = __fdiv_rn(in0, __fsub_rn(__fadd_rn(ag, ap0), in0));
        float wx1 = fmaxf(__fsub_rn(fminf(g.z, p1.z), fmaxf(g.x, p1.x)), 0.0f);
        float wy1 = fmaxf(__fsub_rn(fminf(g.w, p1.w), fmaxf(g.y, p1.y)), 0.0f);
        float in1 = __fmul_rn(wx1, wy1);
        best1 = __fdiv_rn(in1, __fsub_rn(__fadd_rn(ag, ap1), in1));
    }

#pragma unroll 9
    for (int i = 1; i < NGT / 4; ++i) {
        const int m = sub + 4 * i;
        float4 g = sgt[m];
        float ag = sag[m];

        float wx0 = fmaxf(__fsub_rn(fminf(g.z, p0.z), fmaxf(g.x, p0.x)), 0.0f);
        float wy0 = fmaxf(__fsub_rn(fminf(g.w, p0.w), fmaxf(g.y, p0.y)), 0.0f);
        float in0 = __fmul_rn(wx0, wy0);
        float un0 = __fsub_rn(__fadd_rn(ag, ap0), in0);
        if (in0 > __fmul_rd(best0, un0)) {
            float iou = __fdiv_rn(in0, un0);
            if (iou > best0) { best0 = iou; bi0 = m; }
        }

        float wx1 = fmaxf(__fsub_rn(fminf(g.z, p1.z), fmaxf(g.x, p1.x)), 0.0f);
        float wy1 = fmaxf(__fsub_rn(fminf(g.w, p1.w), fmaxf(g.y, p1.y)), 0.0f);
        float in1 = __fmul_rn(wx1, wy1);
        float un1 = __fsub_rn(__fadd_rn(ag, ap1), in1);
        if (in1 > __fmul_rd(best1, un1)) {
            float iou = __fdiv_rn(in1, un1);
            if (iou > best1) { best1 = iou; bi1 = m; }
        }
    }

    // Reduce across the 4 subs: (max value, min index) == sequential first-max
#pragma unroll
    for (int off = 1; off <= 2; off <<= 1) {
        float ob = __shfl_xor_sync(0xffffffffu, best0, off);
        int  obi = __shfl_xor_sync(0xffffffffu, bi0,   off);
        if (ob > best0 || (ob == best0 && obi < bi0)) { best0 = ob; bi0 = obi; }
        ob  = __shfl_xor_sync(0xffffffffu, best1, off);
        obi = __shfl_xor_sync(0xffffffffu, bi1,   off);
        if (ob > best1 || (ob == best1 && obi < bi1)) { best1 = ob; bi1 = obi; }
    }

    const bool fg0 = (best0 >= 0.5f);      // FG_IOU == BG_IOU == 0.5
    const bool fg1 = (best1 >= 0.5f);

    // One converged Threefry per lane:
    //   sub0 -> (k1, r0), sub1 -> (k1, r1), sub2 -> (k2, r0), sub3 -> (k2, r1)
    const uint32_t* kv = keys.v[img];
    uint32_t kk0 = (sub & 2) ? kv[2] : kv[0];
    uint32_t kk1 = (sub & 2) ? kv[3] : kv[1];
    uint32_t rr  = (sub & 1) ? (uint32_t)r1c : (uint32_t)r0;
    uint32_t w0, w1;
    threefry2x32(kk0, kk1, 0u, rr, w0, w1);
    float u = jax_uniform_from_bits(w0 ^ w1);
    float uo = __shfl_xor_sync(0xffffffffu, u, 1);
    float uA = (sub & 1) ? uo : u;     // for r0 (this sub-pair's key)
    float uB = (sub & 1) ? u  : uo;    // for r1

    // Histogram contribution (one entry per proposal, pool = fg ? 0 : 1).
    // sub0: fg/r0  sub1: fg/r1  sub2: bg/r0  sub3: bg/r1
    {
        const bool isFg  = (sub & 1) ? fg1 : fg0;
        const bool inRange = (sub & 1) ? has1 : true;
        const bool want = (sub & 2) ? !isFg : isFg;
        if (inRange && want) {
            int bkt = (int)(u * (float)NBUCKET);
            atomicAdd(&g_hist[(img * 2 + ((sub & 2) >> 1)) * NBUCKET + bkt], 1);
        }
    }

    const unsigned long long INV0 = (0x40000000ull << 32) | (unsigned)r0;
    const unsigned long long INV1 = (0x40000000ull << 32) | (unsigned)r1;
    unsigned long long key0 =
        (((unsigned long long)__float_as_uint(uA)) << 32) | (unsigned)r0;
    unsigned long long key1 =
        (((unsigned long long)__float_as_uint(uB)) << 32) | (unsigned)r1;

    const size_t ib = (size_t)img * NPR;
    if (sub == 0) {
        g_fgkeys[ib + r0] = fg0 ? key0 : INV0;
        if (has1) g_fgkeys[ib + r1] = fg1 ? key1 : INV1;
    } else if (sub == 2) {
        g_bgkeys[ib + r0] = fg0 ? INV0 : key0;
        if (has1) g_bgkeys[ib + r1] = fg1 ? INV1 : key1;
    } else if (sub == 1) {
        g_midx[ib + r0] = bi0;
        if (has1) g_midx[ib + r1] = bi1;
    } else {
        g_labels[ib + r0] = fg0 ? sgc[bi0] : 0;
        if (has1) g_labels[ib + r1] = fg1 ? sgc[bi1] : 0;
    }
}

// ---------------------------------------------------------------------------
// Kernel 2 (fused, SORT-FREE, single key sweep): per-image fg/bg selection
// CONCURRENTLY (warps 0-15 = fg, warps 16-31 = bg, named barriers), then the
// gather/epilogue from SMEM.
//
//  1. load precomputed 1024-bucket histogram from global (+ reset it to zero
//     to restore the replay invariant)
//  2. prefix sums -> cumE[] (exclusive), threshold bucket B (cum >= target)
//  3. single vectorized sweep over keys: compact candidates with bucket <= B,
//     grouped by bucket via atomic per-bucket cursors
//  4. exact rank = cumE[bucket] + #(same-bucket keys < k); keys are unique
//     u64 (score,index) -> total order -> rank < target scatter-writes the
//     index straight into its sorted slot  (== stable argsort prefix)
// ---------------------------------------------------------------------------
#define NB() asm volatile("bar.sync %0, %1;" :: "r"(half + 1), "r"(512) : "memory")

__global__ void select_gather_kernel(const float* __restrict__ gt,
                                     const float* __restrict__ pr,
                                     float* __restrict__ out)
{
    __shared__ unsigned long long cand_fg[FG_CAP];
    __shared__ unsigned long long cand_bg[BG_CAP];
    __shared__ int cumE2[2][NBUCKET + 1];  // exclusive cum (static)
    __shared__ int off2[2][NBUCKET];       // mutable bucket write cursors
    __shared__ int wsum2[2][16];
    __shared__ int bidx[2];
    __shared__ int totals[2];
    __shared__ int sfg[NPOSMAX];
    __shared__ int sbg[BATCH];

    const int img  = blockIdx.x;
    const int tid  = threadIdx.x;  // 1024
    const int half = tid >> 9;     // 0 = fg, 1 = bg
    const int ht   = tid & 511;
    const int lane = tid & 31;
    const int hw   = ht >> 5;      // warp within half, 0..15

    const int target = half ? BATCH : NPOSMAX;
    const int cap    = half ? BG_CAP : FG_CAP;
    unsigned long long* cand = half ? cand_bg : cand_fg;
    const unsigned long long* src = (half ? g_bgkeys : g_fgkeys)
                                    + (size_t)img * NPR;
    int* hist = &g_hist[(img * 2 + half) * NBUCKET];

    if (ht == 0) bidx[half] = NBUCKET - 1;

    // Phase 1: load histogram from global, reset it for the next replay
    const int v0 = hist[2 * ht];
    const int v1 = hist[2 * ht + 1];
    hist[2 * ht]     = 0;
    hist[2 * ht + 1] = 0;

    // Phase 2: scan (each thread owns buckets 2ht, 2ht+1)
    int v = v0 + v1;
#pragma unroll
    for (int off = 1; off < 32; off <<= 1) {
        int o = __shfl_up_sync(0xffffffffu, v, off);
        if (lane >= off) v += o;
    }
    if (lane == 31) wsum2[half][hw] = v;
    NB();
    if (ht < 32) {
        int w = (lane < 16) ? wsum2[half][lane] : 0;
#pragma unroll
        for (int off = 1; off < 32; off <<= 1) {
            int o = __shfl_up_sync(0xffffffffu, w, off);
            if (lane >= off) w += o;
        }
        if (lane < 16) wsum2[half][lane] = w;
    }
    NB();
    const int incl  = v + (hw ? wsum2[half][hw - 1] : 0);  // incl cum @ 2ht+1
    const int excl1 = incl - v1;                            // excl cum @ 2ht+1
    const int excl0 = excl1 - v0;                           // excl cum @ 2ht
    cumE2[half][2 * ht]     = excl0;
    cumE2[half][2 * ht + 1] = excl1;
    off2[half][2 * ht]      = excl0;
    off2[half][2 * ht + 1]  = excl1;
    if (ht == 511) { cumE2[half][NBUCKET] = incl; totals[half] = incl; }
    // threshold bucket: unique b with excl < target <= incl
    if (excl0 < target && excl0 + v0 >= target) bidx[half] = 2 * ht;
    if (excl1 < target && incl >= target)       bidx[half] = 2 * ht + 1;
    NB();
    const int B = bidx[half];

    // Phase 3: single vectorized sweep — compact candidates (bucket <= B)
    const ulonglong2* src2 = reinterpret_cast<const ulonglong2*>(src);
#pragma unroll
    for (int it = 0; it < (NPR / 2 + 511) / 512; ++it) {
        int vi = ht + it * 512;
        if (vi < NPR / 2) {
            ulonglong2 kk = src2[vi];
#pragma unroll
            for (int e = 0; e < 2; ++e) {
                unsigned long long k = e ? kk.y : kk.x;
                uint32_t hi = (uint32_t)(k >> 32);
                if (hi < 0x40000000u) {
                    int b = (int)(__uint_as_float(hi) * (float)NBUCKET);
                    if (b <= B) {
                        int pos = atomicAdd(&off2[half][b], 1);
                        if (pos < cap) cand[pos] = k;
                    }
                }
            }
        }
    }
    NB();
    const int cnt = min(cumE2[half][B + 1], cap);

    // Phase 4: exact rank + scatter into sorted slots
    int* inds = half ? sbg : sfg;
    for (int i = ht; i < cnt; i += 512) {
        unsigned long long k = cand[i];
        int b  = (int)(__uint_as_float((uint32_t)(k >> 32)) * (float)NBUCKET);
        int lo = cumE2[half][b];
        int hiE = min(cumE2[half][b + 1], cnt);
        int rank = lo;
        for (int j = lo; j < hiE; ++j)
            rank += (cand[j] < k);
        if (rank < target) inds[rank] = (int)(unsigned)(k & 0xffffffffu);
    }
    __syncthreads();   // join fg & bg halves

    // Gather / epilogue straight out of SMEM
    if (tid < BATCH) {
        const int slot = tid;
        const int np = min(totals[0], NPOSMAX);
        const int nn = min(totals[1], BATCH - np);
        const bool valid = slot < (np + nn);

        int sampled = 0;
        if (slot < np)   sampled = sfg[slot];
        else if (valid)  sampled = sbg[slot - np];

        const float vmul = valid ? 1.0f : 0.0f;
        const int m = g_midx[(size_t)img * NPR + sampled];
        float4 p = reinterpret_cast<const float4*>(pr)[img * NPR + sampled];
        float4 g = reinterpret_cast<const float4*>(gt)[img * NGT + m];

        float* ob = out + (size_t)(img * BATCH + slot) * 8;
        ob[0] = p.x * vmul;  ob[1] = p.y * vmul;
        ob[2] = p.z * vmul;  ob[3] = p.w * vmul;
        ob[4] = g.x * vmul;  ob[5] = g.y * vmul;
        ob[6] = g.z * vmul;  ob[7] = g.w * vmul;

        const int cls = valid ? g_labels[(size_t)img * NPR + sampled] : -1;
        out[(size_t)NIMG * BATCH * 8 + img * BATCH + slot] = (float)cls;
    }
}

// ---------------------------------------------------------------------------
// Host: per-image (k1, k2) Threefry keys, partitionable mode:
//   root = key(42) = (0, 42)
//   keys[i]  = TF(root, (0, i))
//   k1, k2   = TF(keys[i], (0,0)), TF(keys[i], (0,1))
// ---------------------------------------------------------------------------
static void compute_keys(ImgKeys& out)
{
    for (int i = 0; i < NIMG; ++i) {
        uint32_t ik0, ik1;
        threefry2x32(0u, 42u, 0u, (uint32_t)i, ik0, ik1);
        uint32_t a0, a1, b0, b1;
        threefry2x32(ik0, ik1, 0u, 0u, a0, a1);   // k1
        threefry2x32(ik0, ik1, 0u, 1u, b0, b1);   // k2
        out.v[i][0] = a0; out.v[i][1] = a1;
        out.v[i][2] = b0; out.v[i][3] = b1;
    }
}

extern "C" void kernel_launch(void* const* d_in, const int* in_sizes, int n_in,
                              void* d_out, int out_size)
{
    const float* gt  = (const float*)d_in[0];  // [8,256,4]
    const int*   gtc = (const int*)  d_in[1];  // [8,256]
    const float* pr  = (const float*)d_in[2];  // [8,8000,4]
    float* out = (float*)d_out;

    (void)in_sizes; (void)n_in; (void)out_size;

    ImgKeys keys;
    compute_keys(keys);

    dim3 g1((NPR + 127) / 128, NIMG);      // 63 x 8 blocks, 256 thr each
    match_kernel<<<g1, 256>>>(gt, gtc, pr, keys);
    select_gather_kernel<<<NIMG, 1024>>>(gt, pr, out);
}

// round 9
// speedup vs baseline: 4.4224x; 1.0468x over previous
#include <cuda_runtime.h>
#include <cuda_bf16.h>
#include <cstdint>

// Problem constants
#define NIMG 8
#define NGT  256
#define NPR  8000
#define BATCH 512
#define NPOSMAX 128
#define NBUCKET 1024
#define BCAP 64              // max keys per bucket (mean: bg ~7, fg ~0.8)
#define FG_CAP 512
#define BG_CAP 1024

// ---------------------------------------------------------------------------
// Threefry-2x32 (JAX default PRNG), 20 rounds.
// ---------------------------------------------------------------------------
__host__ __device__ __forceinline__ void threefry2x32(
    uint32_t k0, uint32_t k1, uint32_t x0, uint32_t x1,
    uint32_t& o0, uint32_t& o1)
{
    uint32_t ks0 = k0, ks1 = k1, ks2 = k0 ^ k1 ^ 0x1BD11BDAu;
    uint32_t a = x0 + ks0, b = x1 + ks1;
    const uint32_t rot[2][4] = {{13u,15u,26u,6u},{17u,29u,16u,24u}};
#pragma unroll
    for (int i = 0; i < 5; ++i) {
        const uint32_t* r = rot[i & 1];
#pragma unroll
        for (int q = 0; q < 4; ++q) {
            a += b;
            b = (b << r[q]) | (b >> (32u - r[q]));
            b ^= a;
        }
        uint32_t i1 = (uint32_t)(i + 1);
        uint32_t kA = (i % 3 == 0) ? ks1 : (i % 3 == 1) ? ks2 : ks0;
        uint32_t kB = (i % 3 == 0) ? ks2 : (i % 3 == 1) ? ks0 : ks1;
        a += kA;
        b += kB + i1;
    }
    o0 = a; o1 = b;
}

__host__ __device__ __forceinline__ float jax_uniform_from_bits(uint32_t bits) {
    uint32_t fb = (bits >> 9) | 0x3f800000u;
    float f;
#ifdef __CUDA_ARCH__
    f = __uint_as_float(fb);
#else
    union { uint32_t u; float f; } c; c.u = fb; f = c.f;
#endif
    return f - 1.0f;
}

struct ImgKeys {
    uint32_t v[NIMG][4];   // per image: k1 (2 words), k2 (2 words)
};

// ---------------------------------------------------------------------------
// Scratch (device globals — no allocation allowed).
// g_hist is all-zeros at module load; select_gather_kernel restores it to
// zeros every call, so every replay sees the identical initial state.
// g_bkeys slots are gated by g_hist counts, so they need no clearing.
// ---------------------------------------------------------------------------
__device__ int                g_midx[NIMG * NPR];
__device__ int                g_labels[NIMG * NPR];
__device__ int                g_hist[NIMG * 2 * NBUCKET];
__device__ unsigned long long g_bkeys[NIMG * 2 * NBUCKET * BCAP];

// ---------------------------------------------------------------------------
// Kernel 1: IoU matching + labels + PRNG keys scattered into buckets.
// 4 threads per proposal-pair lane-group; thread `sub` handles GT subset
// m = sub, sub+4, ... for TWO proposals (r0, r1 = r0+64). First eval peeled
// (one exact division) so the loop invariant is best >= 0, collapsing
// division-avoidance to one test:
//   inter <= __fmul_rd(best, uni) <= best*uni  =>  rn(inter/uni) <= best
//   => strict '>' update impossible => safe to skip.  Bit-identical to ref.
//
// Each proposal publishes exactly ONE key into its pool's bucket array:
// the atomicAdd on the histogram returns the bucket slot. Sub roles:
//   sub0 -> (k1-draw, r0): publishes iff fg0     (fg pool)
//   sub1 -> (k1-draw, r1): publishes iff fg1     (fg pool)
//   sub2 -> (k2-draw, r0): publishes iff !fg0    (bg pool)
//   sub3 -> (k2-draw, r1): publishes iff !fg1    (bg pool)
// ---------------------------------------------------------------------------
__global__ void match_kernel(const float* __restrict__ gt,
                             const int*   __restrict__ gtc,
                             const float* __restrict__ pr,
                             ImgKeys keys)
{
    const int img = blockIdx.y;
    const int tid = threadIdx.x;           // 256 threads = 64 pairs x 4 subs
    const int sub = tid & 3;
    const int pid = tid >> 2;              // 0..63
    const int base = blockIdx.x * 128;     // 63 blocks cover 8064 >= 8000
    const int r0 = base + pid;
    const int r1 = base + 64 + pid;
    const bool has1 = (r1 < NPR);
    const int r1c = has1 ? r1 : (NPR - 1);

    __shared__ float4 sgt[NGT];
    __shared__ float  sag[NGT];
    __shared__ int    sgc[NGT];

    {
        float4 g = reinterpret_cast<const float4*>(gt)[img * NGT + tid];
        sgt[tid] = g;
        sag[tid] = __fmul_rn(__fsub_rn(g.z, g.x), __fsub_rn(g.w, g.y));
        sgc[tid] = gtc[img * NGT + tid];
    }
    __syncthreads();

    float4 p0 = reinterpret_cast<const float4*>(pr)[img * NPR + r0];
    float4 p1 = reinterpret_cast<const float4*>(pr)[img * NPR + r1c];
    const float ap0 = __fmul_rn(__fsub_rn(p0.z, p0.x), __fsub_rn(p0.w, p0.y));
    const float ap1 = __fmul_rn(__fsub_rn(p1.z, p1.x), __fsub_rn(p1.w, p1.y));

    float best0, best1;
    int   bi0 = sub, bi1 = sub;
    {   // peeled first eval (m = sub): unconditional exact division
        float4 g = sgt[sub];
        float ag = sag[sub];
        float wx0 = fmaxf(__fsub_rn(fminf(g.z, p0.z), fmaxf(g.x, p0.x)), 0.0f);
        float wy0 = fmaxf(__fsub_rn(fminf(g.w, p0.w), fmaxf(g.y, p0.y)), 0.0f);
        float in0 = __fmul_rn(wx0, wy0);
        best0 = __fdiv_rn(in0, __fsub_rn(__fadd_rn(ag, ap0), in0));
        float wx1 = fmaxf(__fsub_rn(fminf(g.z, p1.z), fmaxf(g.x, p1.x)), 0.0f);
        float wy1 = fmaxf(__fsub_rn(fminf(g.w, p1.w), fmaxf(g.y, p1.y)), 0.0f);
        float in1 = __fmul_rn(wx1, wy1);
        best1 = __fdiv_rn(in1, __fsub_rn(__fadd_rn(ag, ap1), in1));
    }

#pragma unroll 9
    for (int i = 1; i < NGT / 4; ++i) {
        const int m = sub + 4 * i;
        float4 g = sgt[m];
        float ag = sag[m];

        float wx0 = fmaxf(__fsub_rn(fminf(g.z, p0.z), fmaxf(g.x, p0.x)), 0.0f);
        float wy0 = fmaxf(__fsub_rn(fminf(g.w, p0.w), fmaxf(g.y, p0.y)), 0.0f);
        float in0 = __fmul_rn(wx0, wy0);
        float un0 = __fsub_rn(__fadd_rn(ag, ap0), in0);
        if (in0 > __fmul_rd(best0, un0)) {
            float iou = __fdiv_rn(in0, un0);
            if (iou > best0) { best0 = iou; bi0 = m; }
        }

        float wx1 = fmaxf(__fsub_rn(fminf(g.z, p1.z), fmaxf(g.x, p1.x)), 0.0f);
        float wy1 = fmaxf(__fsub_rn(fminf(g.w, p1.w), fmaxf(g.y, p1.y)), 0.0f);
        float in1 = __fmul_rn(wx1, wy1);
        float un1 = __fsub_rn(__fadd_rn(ag, ap1), in1);
        if (in1 > __fmul_rd(best1, un1)) {
            float iou = __fdiv_rn(in1, un1);
            if (iou > best1) { best1 = iou; bi1 = m; }
        }
    }

    // Reduce across the 4 subs: (max value, min index) == sequential first-max
#pragma unroll
    for (int off = 1; off <= 2; off <<= 1) {
        float ob = __shfl_xor_sync(0xffffffffu, best0, off);
        int  obi = __shfl_xor_sync(0xffffffffu, bi0,   off);
        if (ob > best0 || (ob == best0 && obi < bi0)) { best0 = ob; bi0 = obi; }
        ob  = __shfl_xor_sync(0xffffffffu, best1, off);
        obi = __shfl_xor_sync(0xffffffffu, bi1,   off);
        if (ob > best1 || (ob == best1 && obi < bi1)) { best1 = ob; bi1 = obi; }
    }

    const bool fg0 = (best0 >= 0.5f);      // FG_IOU == BG_IOU == 0.5
    const bool fg1 = (best1 >= 0.5f);

    // One converged Threefry per lane (this sub's own draw+proposal):
    const uint32_t* kv = keys.v[img];
    uint32_t kk0 = (sub & 2) ? kv[2] : kv[0];
    uint32_t kk1 = (sub & 2) ? kv[3] : kv[1];
    const int  myR   = (sub & 1) ? r1c : r0;
    const bool myFg  = (sub & 1) ? fg1 : fg0;
    const bool myIn  = (sub & 1) ? has1 : true;
    const int  pool  = (sub & 2) >> 1;          // 0 = fg draw, 1 = bg draw
    uint32_t w0, w1;
    threefry2x32(kk0, kk1, 0u, (uint32_t)myR, w0, w1);
    float u = jax_uniform_from_bits(w0 ^ w1);

    // Publish this proposal's key into its pool's bucket (if it belongs here)
    const bool publish = myIn && (pool == 0 ? myFg : !myFg);
    if (publish) {
        int bkt = (int)(u * (float)NBUCKET);
        int hidx = (img * 2 + pool) * NBUCKET + bkt;
        int pos = atomicAdd(&g_hist[hidx], 1);
        if (pos < BCAP) {
            unsigned long long k =
                (((unsigned long long)__float_as_uint(u)) << 32) | (unsigned)myR;
            g_bkeys[(size_t)hidx * BCAP + pos] = k;
        }
    }

    const size_t ib = (size_t)img * NPR;
    if (sub == 1) {
        g_midx[ib + r0] = bi0;
        if (has1) g_midx[ib + r1] = bi1;
    } else if (sub == 3) {
        g_labels[ib + r0] = fg0 ? sgc[bi0] : 0;
        if (has1) g_labels[ib + r1] = fg1 ? sgc[bi1] : 0;
    }
}

// ---------------------------------------------------------------------------
// Kernel 2 (fused, SWEEP-FREE): per-image fg/bg selection CONCURRENTLY
// (warps 0-15 = fg, warps 16-31 = bg, named barriers), then gather from SMEM.
//
//  1. load precomputed 1024-bucket histogram (+ reset to zero for replay)
//  2. prefix sums -> cumE[] (exclusive), threshold bucket B (cum >= target)
//  3. read ONLY buckets <= B from the bucketed key array into SMEM at
//     cand[cumE[b] + j]  (~target + one-bucket keys total)
//  4. exact rank = cumE[bucket] + #(same-bucket keys < k); keys are unique
//     u64 (score,index) -> total order -> rank < target scatter-writes the
//     index into its sorted slot (== stable argsort prefix). Within-bucket
//     atomic order is nondeterministic but rank is order-invariant.
// ---------------------------------------------------------------------------
#define NB() asm volatile("bar.sync %0, %1;" :: "r"(half + 1), "r"(512) : "memory")

__global__ void select_gather_kernel(const float* __restrict__ gt,
                                     const float* __restrict__ pr,
                                     float* __restrict__ out)
{
    __shared__ unsigned long long cand_fg[FG_CAP];
    __shared__ unsigned long long cand_bg[BG_CAP];
    __shared__ int cumE2[2][NBUCKET + 1];
    __shared__ int wsum2[2][16];
    __shared__ int bidx[2];
    __shared__ int totals[2];
    __shared__ int sfg[NPOSMAX];
    __shared__ int sbg[BATCH];

    const int img  = blockIdx.x;
    const int tid  = threadIdx.x;  // 1024
    const int half = tid >> 9;     // 0 = fg, 1 = bg
    const int ht   = tid & 511;
    const int lane = tid & 31;
    const int hw   = ht >> 5;      // warp within half, 0..15

    const int target = half ? BATCH : NPOSMAX;
    const int cap    = half ? BG_CAP : FG_CAP;
    unsigned long long* cand = half ? cand_bg : cand_fg;
    int* hist = &g_hist[(img * 2 + half) * NBUCKET];
    const unsigned long long* bsrc =
        &g_bkeys[(size_t)(img * 2 + half) * NBUCKET * BCAP];

    if (ht == 0) bidx[half] = NBUCKET - 1;

    // Phase 1: load histogram from global, reset it for the next replay
    const int v0 = hist[2 * ht];
    const int v1 = hist[2 * ht + 1];
    hist[2 * ht]     = 0;
    hist[2 * ht + 1] = 0;

    // Phase 2: scan (each thread owns buckets 2ht, 2ht+1)
    int v = v0 + v1;
#pragma unroll
    for (int off = 1; off < 32; off <<= 1) {
        int o = __shfl_up_sync(0xffffffffu, v, off);
        if (lane >= off) v += o;
    }
    if (lane == 31) wsum2[half][hw] = v;
    NB();
    if (ht < 32) {
        int w = (lane < 16) ? wsum2[half][lane] : 0;
#pragma unroll
        for (int off = 1; off < 32; off <<= 1) {
            int o = __shfl_up_sync(0xffffffffu, w, off);
            if (lane >= off) w += o;
        }
        if (lane < 16) wsum2[half][lane] = w;
    }
    NB();
    const int incl  = v + (hw ? wsum2[half][hw - 1] : 0);  // incl cum @ 2ht+1
    const int excl1 = incl - v1;                            // excl cum @ 2ht+1
    const int excl0 = excl1 - v0;                           // excl cum @ 2ht
    cumE2[half][2 * ht]     = excl0;
    cumE2[half][2 * ht + 1] = excl1;
    if (ht == 511) { cumE2[half][NBUCKET] = incl; totals[half] = incl; }
    // threshold bucket: unique b with excl < target <= incl
    if (excl0 < target && excl0 + v0 >= target) bidx[half] = 2 * ht;
    if (excl1 < target && incl >= target)       bidx[half] = 2 * ht + 1;
    NB();
    const int B = bidx[half];

    // Phase 3: fetch only buckets <= B into SMEM at cand[cumE[b] + j]
    for (int b = ht; b <= B; b += 512) {
        int lo = cumE2[half][b];
        int n  = min(cumE2[half][b + 1] - lo, BCAP);
        const unsigned long long* bp = bsrc + (size_t)b * BCAP;
        for (int j = 0; j < n; ++j) {
            int pos = lo + j;
            if (pos < cap) cand[pos] = bp[j];
        }
    }
    NB();
    const int cnt = min(cumE2[half][B + 1], cap);

    // Phase 4: exact rank + scatter into sorted slots
    int* inds = half ? sbg : sfg;
    for (int i = ht; i < cnt; i += 512) {
        unsigned long long k = cand[i];
        int b  = (int)(__uint_as_float((uint32_t)(k >> 32)) * (float)NBUCKET);
        int lo = cumE2[half][b];
        int hiE = min(cumE2[half][b + 1], cnt);
        int rank = lo;
        for (int j = lo; j < hiE; ++j)
            rank += (cand[j] < k);
        if (rank < target) inds[rank] = (int)(unsigned)(k & 0xffffffffu);
    }
    __syncthreads();   // join fg & bg halves

    // Gather / epilogue straight out of SMEM
    if (tid < BATCH) {
        const int slot = tid;
        const int np = min(totals[0], NPOSMAX);
        const int nn = min(totals[1], BATCH - np);
        const bool valid = slot < (np + nn);

        int sampled = 0;
        if (slot < np)   sampled = sfg[slot];
        else if (valid)  sampled = sbg[slot - np];

        const float vmul = valid ? 1.0f : 0.0f;
        const int m = g_midx[(size_t)img * NPR + sampled];
        float4 p = reinterpret_cast<const float4*>(pr)[img * NPR + sampled];
        float4 g = reinterpret_cast<const float4*>(gt)[img * NGT + m];

        float* ob = out + (size_t)(img * BATCH + slot) * 8;
        ob[0] = p.x * vmul;  ob[1] = p.y * vmul;
        ob[2] = p.z * vmul;  ob[3] = p.w * vmul;
        ob[4] = g.x * vmul;  ob[5] = g.y * vmul;
        ob[6] = g.z * vmul;  ob[7] = g.w * vmul;

        const int cls = valid ? g_labels[(size_t)img * NPR + sampled] : -1;
        out[(size_t)NIMG * BATCH * 8 + img * BATCH + slot] = (float)cls;
    }
}

// ---------------------------------------------------------------------------
// Host: per-image (k1, k2) Threefry keys, partitionable mode:
//   root = key(42) = (0, 42)
//   keys[i]  = TF(root, (0, i))
//   k1, k2   = TF(keys[i], (0,0)), TF(keys[i], (0,1))
// ---------------------------------------------------------------------------
static void compute_keys(ImgKeys& out)
{
    for (int i = 0; i < NIMG; ++i) {
        uint32_t ik0, ik1;
        threefry2x32(0u, 42u, 0u, (uint32_t)i, ik0, ik1);
        uint32_t a0, a1, b0, b1;
        threefry2x32(ik0, ik1, 0u, 0u, a0, a1);   // k1
        threefry2x32(ik0, ik1, 0u, 1u, b0, b1);   // k2
        out.v[i][0] = a0; out.v[i][1] = a1;
        out.v[i][2] = b0; out.v[i][3] = b1;
    }
}

extern "C" void kernel_launch(void* const* d_in, const int* in_sizes, int n_in,
                              void* d_out, int out_size)
{
    const float* gt  = (const float*)d_in[0];  // [8,256,4]
    const int*   gtc = (const int*)  d_in[1];  // [8,256]
    const float* pr  = (const float*)d_in[2];  // [8,8000,4]
    float* out = (float*)d_out;

    (void)in_sizes; (void)n_in; (void)out_size;

    ImgKeys keys;
    compute_keys(keys);

    dim3 g1((NPR + 127) / 128, NIMG);      // 63 x 8 blocks, 256 thr each
    match_kernel<<<g1, 256>>>(gt, gtc, pr, keys);
    select_gather_kernel<<<NIMG, 1024>>>(gt, pr, out);
}